// round 11
// baseline (speedup 1.0000x reference)
#include <cuda_runtime.h>
#include <cuda_fp16.h>
#include <math.h>
#include <float.h>
#include <stdint.h>

// ---------------- problem constants ----------------
#define TOKENS_TOTAL (32*2048)
#define IN_DIM   128
#define HID      64
#define OUT_DIM  64
#define CODEBOOK 2048

#define TB       128
#define NTHREADS 256
#define NBLOCKS  (TOKENS_TOTAL/TB)     // 512
#define XT_STRIDE 130
#define CCH      64                     // codes per staged chunk
#define NCH      (CODEBOOK/CCH)         // 32

// output layout: msg ++ idx(as float) ++ loss
#define MSG_ELEMS ((size_t)TOKENS_TOTAL*OUT_DIM)
#define IDX_OFF   MSG_ELEMS
#define LOSS_OFF  (MSG_ELEMS + TOKENS_TOTAL)

// ---------------- smem layout (word offsets; 1 word = 4B) ----------------
#define OFF_XT   2048                   // 64 x 130 f -> end 10368 (words 0..2048 free)
#define OFF_B    10368                  // 3 bufs x (hi 64x36 + lo 64x36) = 13824 w -> 24192
#define B_ROW_W   36
#define B_TILE_W  (CCH*B_ROW_W)         // 2304
#define B_BUF_W   (2*B_TILE_W)          // 4608 (hi tile then lo tile)
#define OFF_E2   24192                  // 2048 f -> 26240
// MLP-phase overlays (time-disjoint with B/E2 regions)
#define OFF_W    10368                  // weights (<= 8192 f), MLP only
#define OFF_OBS  18560                  // obs tile / h2 (8192 f), MLP only -> 26752
#define OFF_H1   2048                   // h1 overlays XT (XT written later)
#define SMEM_FLOATS 26752               // 107008 B ; x2 CTAs fits 228KB

__device__ float g_partial[NBLOCKS];
__device__ int   g_done = 0;

// ---------------- fp16 split helpers ----------------
__device__ __forceinline__ void split_h2(float x0, float x1, uint32_t& h, uint32_t& l) {
    __half h0 = __float2half_rn(x0);
    __half h1 = __float2half_rn(x1);
    float  l0 = x0 - __half2float(h0);
    float  l1 = x1 - __half2float(h1);
    __half2 hh = __halves2half2(h0, h1);
    __half2 ll = __floats2half2_rn(l0, l1);
    h = *(uint32_t*)&hh;
    l = *(uint32_t*)&ll;
}

__device__ __forceinline__ void mma16(float* c, const uint32_t* a, uint32_t b0, uint32_t b1) {
    asm volatile(
        "mma.sync.aligned.m16n8k16.row.col.f32.f16.f16.f32 "
        "{%0,%1,%2,%3}, {%4,%5,%6,%7}, {%8,%9}, {%0,%1,%2,%3};"
        : "+f"(c[0]), "+f"(c[1]), "+f"(c[2]), "+f"(c[3])
        : "r"(a[0]), "r"(a[1]), "r"(a[2]), "r"(a[3]), "r"(b0), "r"(b1));
}

// packed fp32x2 (MLP)
__device__ __forceinline__ unsigned long long dup2(float x) {
    unsigned long long r; asm("mov.b64 %0, {%1, %1};" : "=l"(r) : "f"(x)); return r;
}
__device__ __forceinline__ void ffma2(unsigned long long& d, unsigned long long a, unsigned long long b) {
    asm("fma.rn.f32x2 %0, %1, %2, %0;" : "+l"(d) : "l"(a), "l"(b));
}
__device__ __forceinline__ float lo32(unsigned long long v) { return __uint_as_float((unsigned)v); }
__device__ __forceinline__ float hi32(unsigned long long v) { return __uint_as_float((unsigned)(v >> 32)); }

// ---------------- MLP layer (proven rounds 1..10) ----------------
template<int KD, int NT, int OUTMODE, bool RELU>
__device__ __forceinline__ void mlp_layer(const float* in_s, int in_stride,
                                          const float* w_s, const float* __restrict__ b_g,
                                          float* out_s, int tid)
{
    const int jg = tid & 7;
    const int tg = tid >> 3;
    float bj[4][2];
#pragma unroll
    for (int jj = 0; jj < 4; jj++) {
        int j0 = jg*2 + 16*jj;
        bj[jj][0] = __ldg(b_g + j0);
        bj[jj][1] = __ldg(b_g + j0 + 1);
    }
    unsigned long long acc[NT][4];
#pragma unroll
    for (int it = 0; it < NT; it++)
#pragma unroll
        for (int jj = 0; jj < 4; jj++) acc[it][jj] = 0ULL;

#pragma unroll 4
    for (int k0 = 0; k0 < KD; k0 += 4) {
        float xin[NT][4];
#pragma unroll
        for (int it = 0; it < NT; it++) {
            float4 v = *(const float4*)(in_s + (tg*NT + it)*in_stride + k0);
            xin[it][0] = v.x; xin[it][1] = v.y; xin[it][2] = v.z; xin[it][3] = v.w;
        }
#pragma unroll
        for (int kk = 0; kk < 4; kk++) {
            unsigned long long wp[4];
#pragma unroll
            for (int jj = 0; jj < 4; jj++)
                wp[jj] = *(const unsigned long long*)(w_s + (k0+kk)*64 + jg*2 + 16*jj);
#pragma unroll
            for (int it = 0; it < NT; it++) {
                unsigned long long xd = dup2(xin[it][kk]);
#pragma unroll
                for (int jj = 0; jj < 4; jj++) ffma2(acc[it][jj], xd, wp[jj]);
            }
        }
    }
#pragma unroll
    for (int it = 0; it < NT; it++) {
        int t = tg*NT + it;
#pragma unroll
        for (int jj = 0; jj < 4; jj++) {
            int j0 = jg*2 + 16*jj;
            float v0 = lo32(acc[it][jj]) + bj[jj][0];
            float v1 = hi32(acc[it][jj]) + bj[jj][1];
            if (RELU) { v0 = fmaxf(v0, 0.0f); v1 = fmaxf(v1, 0.0f); }
            if (OUTMODE == 0) {
                out_s[t*64 + j0]     = v0;
                out_s[t*64 + j0 + 1] = v1;
            } else {
                out_s[j0*XT_STRIDE + t]       = v0;
                out_s[(j0 + 1)*XT_STRIDE + t] = v1;
            }
        }
    }
}

// ---------------- staging: raw cb -> split fp16 hi/lo, fragment-order rows + e2 ----------------
// thread: c = tid>>2 (code in chunk), q' = tid&3 (owns elements q'*16 .. q'*16+15)
__device__ __forceinline__ void b_ldg_raw(const float* __restrict__ cb, int ch, int tid, float4* v) {
    int c = tid >> 2, qp = tid & 3;
    const float4* p = (const float4*)(cb + (size_t)(ch*CCH + c)*OUT_DIM + qp*16);
#pragma unroll
    for (int i = 0; i < 4; i++) v[i] = __ldg(p + i);
}
__device__ __forceinline__ void b_sts_split(uint32_t* bbuf, float* e2s, int code_base,
                                            int tid, const float4* v) {
    int c = tid >> 2, qp = tid & 3;
    // word j (elements 2j,2j+1 of this thread's 16) -> slot (j&3)*8 + qp*2 + (j>>2)
    // pair p: (j=p, j=p+4) -> adjacent slots p*8 + qp*2, +1
    uint32_t h[8], l[8];
    split_h2(v[0].x, v[0].y, h[0], l[0]);   // j=0
    split_h2(v[0].z, v[0].w, h[1], l[1]);   // j=1
    split_h2(v[1].x, v[1].y, h[2], l[2]);   // j=2
    split_h2(v[1].z, v[1].w, h[3], l[3]);   // j=3
    split_h2(v[2].x, v[2].y, h[4], l[4]);   // j=4
    split_h2(v[2].z, v[2].w, h[5], l[5]);   // j=5
    split_h2(v[3].x, v[3].y, h[6], l[6]);   // j=6
    split_h2(v[3].z, v[3].w, h[7], l[7]);   // j=7
    uint32_t* row = bbuf + c*B_ROW_W + qp*2;
#pragma unroll
    for (int p = 0; p < 4; p++) {
        *(uint2*)(row + p*8)            = make_uint2(h[p], h[p+4]);
        *(uint2*)(row + B_TILE_W + p*8) = make_uint2(l[p], l[p+4]);
    }
    // e2 partial (same per-float4 order as previous prep kernel)
    float sq = 0.0f;
#pragma unroll
    for (int i = 0; i < 4; i++)
        sq += v[i].x*v[i].x + v[i].y*v[i].y + v[i].z*v[i].z + v[i].w*v[i].w;
    sq += __shfl_xor_sync(0xffffffffu, sq, 1);
    sq += __shfl_xor_sync(0xffffffffu, sq, 2);
    if (qp == 0) e2s[code_base + c] = sq;
}

// ---------------- the ONE kernel ----------------
__global__ void __launch_bounds__(NTHREADS, 2)
vq_main(const float* __restrict__ obs,
        const float* __restrict__ W1, const float* __restrict__ b1,
        const float* __restrict__ W2, const float* __restrict__ b2,
        const float* __restrict__ W3, const float* __restrict__ b3,
        const float* __restrict__ cb,
        float* __restrict__ out)
{
    extern __shared__ float sm[];
    const int tid  = threadIdx.x;
    const int wid  = tid >> 5;
    const int lane = tid & 31;
    const int r    = lane >> 2;
    const int q    = lane & 3;
    const int tok0 = blockIdx.x * TB;

    // ================= MLP (FFMA2, bit-identical to prior rounds) =================
    {
        const float4* w4 = (const float4*)W1;
        float4* d4 = (float4*)(sm + OFF_W);
        for (int i = tid; i < (IN_DIM*HID)/4; i += NTHREADS) d4[i] = w4[i];
    }
    for (int half = 0; half < 2; half++) {
        __syncthreads();
        const float4* o4 = (const float4*)(obs + (size_t)(tok0 + half*64) * IN_DIM);
        float4* d4 = (float4*)(sm + OFF_OBS);
        for (int i = tid; i < (64*IN_DIM)/4; i += NTHREADS) d4[i] = o4[i];
        __syncthreads();
        mlp_layer<IN_DIM, 2, 0, true>(sm + OFF_OBS, IN_DIM, sm + OFF_W, b1,
                                      sm + OFF_H1 + half*64*HID, tid);
    }
    __syncthreads();
    {
        const float4* w4 = (const float4*)W2;
        float4* d4 = (float4*)(sm + OFF_W);
        for (int i = tid; i < (HID*HID)/4; i += NTHREADS) d4[i] = w4[i];
    }
    __syncthreads();
    mlp_layer<HID, 4, 0, true>(sm + OFF_H1, HID, sm + OFF_W, b2, sm + OFF_OBS, tid);
    __syncthreads();
    {
        const float4* w4 = (const float4*)W3;
        float4* d4 = (float4*)(sm + OFF_W);
        for (int i = tid; i < (HID*OUT_DIM)/4; i += NTHREADS) d4[i] = w4[i];
    }
    __syncthreads();
    mlp_layer<HID, 4, 1, false>(sm + OFF_OBS, HID, sm + OFF_W, b3, sm + OFF_XT, tid);
    __syncthreads();

    // ========== A fragments (m16 x k64, fp16 hi/lo) ==========
    const float* xsT = sm + OFF_XT;
    const int tokw = wid * 16;
    uint32_t Ah[4][4], Al[4][4];
#pragma unroll
    for (int kb = 0; kb < 4; kb++) {
        int k0 = kb*16;
        const float* x0 = xsT + tokw;
        float v00 = x0[(k0 + 2*q    )*XT_STRIDE + r];
        float v01 = x0[(k0 + 2*q + 1)*XT_STRIDE + r];
        float v10 = x0[(k0 + 2*q    )*XT_STRIDE + r + 8];
        float v11 = x0[(k0 + 2*q + 1)*XT_STRIDE + r + 8];
        float v20 = x0[(k0 + 2*q + 8)*XT_STRIDE + r];
        float v21 = x0[(k0 + 2*q + 9)*XT_STRIDE + r];
        float v30 = x0[(k0 + 2*q + 8)*XT_STRIDE + r + 8];
        float v31 = x0[(k0 + 2*q + 9)*XT_STRIDE + r + 8];
        split_h2(v00, v01, Ah[kb][0], Al[kb][0]);
        split_h2(v10, v11, Ah[kb][1], Al[kb][1]);
        split_h2(v20, v21, Ah[kb][2], Al[kb][2]);
        split_h2(v30, v31, Ah[kb][3], Al[kb][3]);
    }

    // ================= VQ: fp16 m16n8k16 3-term, triple buffer =================
    float best_d0 = FLT_MAX, best_d1 = FLT_MAX;
    int   best_c0 = 0,       best_c1 = 0;

    uint32_t* bw  = (uint32_t*)(sm + OFF_B);
    float*    e2s = sm + OFF_E2;

    {   // prologue: stage chunk 0 (split + e2)
        float4 st[4];
        b_ldg_raw(cb, 0, tid, st);
        b_sts_split(bw, e2s, 0, tid, st);
        __syncthreads();
    }

    for (int ch = 0; ch < NCH; ch++) {
        const int buf = ch % 3;
        float4 pv[4];
        const bool more = (ch + 1 < NCH);
        if (more) b_ldg_raw(cb, ch + 1, tid, pv);

        const uint32_t* bb = bw + buf*B_BUF_W;

#pragma unroll
        for (int grp = 0; grp < 2; grp++) {
#pragma unroll
            for (int gp = 0; gp < 2; gp++) {
                const uint32_t* pa = bb + (grp*32 + gp*16 + r)*B_ROW_W + q*8;
                const uint32_t* pb = pa + 8*B_ROW_W;
                uint4 h0a = *(const uint4*)(pa);
                uint4 h1a = *(const uint4*)(pa + 4);
                uint4 h0b = *(const uint4*)(pb);
                uint4 h1b = *(const uint4*)(pb + 4);
                uint4 l0a = *(const uint4*)(pa + B_TILE_W);
                uint4 l1a = *(const uint4*)(pa + B_TILE_W + 4);
                uint4 l0b = *(const uint4*)(pb + B_TILE_W);
                uint4 l1b = *(const uint4*)(pb + B_TILE_W + 4);

                float aMa[4]={0,0,0,0}, aMb[4]={0,0,0,0};
                float aCa[4]={0,0,0,0}, aCb[4]={0,0,0,0};
                float aDa[4]={0,0,0,0}, aDb[4]={0,0,0,0};

                mma16(aMa, Ah[0], h0a.x, h0a.y);  mma16(aMb, Ah[0], h0b.x, h0b.y);
                mma16(aCa, Ah[0], l0a.x, l0a.y);  mma16(aCb, Ah[0], l0b.x, l0b.y);
                mma16(aDa, Al[0], h0a.x, h0a.y);  mma16(aDb, Al[0], h0b.x, h0b.y);

                mma16(aMa, Ah[1], h0a.z, h0a.w);  mma16(aMb, Ah[1], h0b.z, h0b.w);
                mma16(aCa, Ah[1], l0a.z, l0a.w);  mma16(aCb, Ah[1], l0b.z, l0b.w);
                mma16(aDa, Al[1], h0a.z, h0a.w);  mma16(aDb, Al[1], h0b.z, h0b.w);

                mma16(aMa, Ah[2], h1a.x, h1a.y);  mma16(aMb, Ah[2], h1b.x, h1b.y);
                mma16(aCa, Ah[2], l1a.x, l1a.y);  mma16(aCb, Ah[2], l1b.x, l1b.y);
                mma16(aDa, Al[2], h1a.x, h1a.y);  mma16(aDb, Al[2], h1b.x, h1b.y);

                mma16(aMa, Ah[3], h1a.z, h1a.w);  mma16(aMb, Ah[3], h1b.z, h1b.w);
                mma16(aCa, Ah[3], l1a.z, l1a.w);  mma16(aCb, Ah[3], l1b.z, l1b.w);
                mma16(aDa, Al[3], h1a.z, h1a.w);  mma16(aDb, Al[3], h1b.z, h1b.w);

#pragma unroll
                for (int half = 0; half < 2; half++) {
                    const float* aM = half ? aMb : aMa;
                    const float* aC = half ? aCb : aCa;
                    const float* aD = half ? aDb : aDa;
                    int code0 = ch*CCH + grp*32 + (gp*2 + half)*8 + 2*q;
                    float e20 = e2s[code0];
                    float e21 = e2s[code0 + 1];
                    float s0 = aM[0] + aC[0] + aD[0];
                    float s1 = aM[1] + aC[1] + aD[1];
                    float s2 = aM[2] + aC[2] + aD[2];
                    float s3 = aM[3] + aC[3] + aD[3];
                    float d0 = fmaf(-2.0f, s0, e20);
                    float d1 = fmaf(-2.0f, s1, e21);
                    float d2 = fmaf(-2.0f, s2, e20);
                    float d3 = fmaf(-2.0f, s3, e21);
                    if (d0 < best_d0) { best_d0 = d0; best_c0 = code0; }
                    if (d1 < best_d0) { best_d0 = d1; best_c0 = code0 + 1; }
                    if (d2 < best_d1) { best_d1 = d2; best_c1 = code0; }
                    if (d3 < best_d1) { best_d1 = d3; best_c1 = code0 + 1; }
                }
            }
        }

        if (more) b_sts_split(bw + ((ch + 1) % 3)*B_BUF_W, e2s, (ch + 1)*CCH, tid, pv);
        __syncthreads();
    }

    // ---- cross-lane argmin, tie-break smaller code ----
#pragma unroll
    for (int m = 1; m <= 2; m <<= 1) {
        float od0 = __shfl_xor_sync(0xffffffffu, best_d0, m);
        int   oc0 = __shfl_xor_sync(0xffffffffu, best_c0, m);
        float od1 = __shfl_xor_sync(0xffffffffu, best_d1, m);
        int   oc1 = __shfl_xor_sync(0xffffffffu, best_c1, m);
        if (od0 < best_d0 || (od0 == best_d0 && oc0 < best_c0)) { best_d0 = od0; best_c0 = oc0; }
        if (od1 < best_d1 || (od1 == best_d1 && oc1 < best_c1)) { best_d1 = od1; best_c1 = oc1; }
    }

    int* sIdx = (int*)sm;                // words 0..128
    if (q == 0) {
        int t0 = tokw + r;
        sIdx[t0]     = best_c0;
        sIdx[t0 + 8] = best_c1;
        out[IDX_OFF + (size_t)(tok0 + t0)]     = (float)best_c0;
        out[IDX_OFF + (size_t)(tok0 + t0 + 8)] = (float)best_c1;
    }
    __syncthreads();

    // ---- msg write + commitment-loss partial ----
    float part = 0.0f;
    for (int f = tid; f < TB*OUT_DIM; f += NTHREADS) {
        int t = f >> 6, j = f & 63;
        int c = sIdx[t];
        float qv = __ldg(cb + (size_t)c * OUT_DIM + j);
        float xv = xsT[j*XT_STRIDE + t];
        out[(size_t)(tok0 + t)*OUT_DIM + j] = xv + (qv - xv);
        float dd = qv - xv;
        part += dd * dd;
    }
#pragma unroll
    for (int o = 16; o > 0; o >>= 1)
        part += __shfl_down_sync(0xffffffffu, part, o);
    __shared__ float swred[8];
    __shared__ int isLast;
    if ((tid & 31) == 0) swred[tid >> 5] = part;
    __syncthreads();
    if (tid == 0) {
        float s = 0.0f;
#pragma unroll
        for (int w = 0; w < 8; w++) s += swred[w];
        g_partial[blockIdx.x] = s;
        __threadfence();
        isLast = (atomicAdd(&g_done, 1) == NBLOCKS - 1);
    }
    __syncthreads();

    // ---- last block: deterministic loss reduction (bit-identical tree to old loss_reduce) ----
    if (isLast) {
        volatile float* gp = g_partial;
        float* red = sm + 512;
        red[tid] = gp[tid] + gp[tid + NTHREADS];
        __syncthreads();
        for (int o = NTHREADS/2; o > 0; o >>= 1) {
            if (tid < o) red[tid] += red[tid + o];
            __syncthreads();
        }
        if (tid == 0) {
            out[LOSS_OFF] = red[0] * (1.0f / (float)MSG_ELEMS);
            g_done = 0;   // reset for next graph replay
        }
    }
}

extern "C" void kernel_launch(void* const* d_in, const int* in_sizes, int n_in,
                              void* d_out, int out_size)
{
    const float* obs = (const float*)d_in[0];
    const float* W1  = (const float*)d_in[1];
    const float* b1  = (const float*)d_in[2];
    const float* W2  = (const float*)d_in[3];
    const float* b2  = (const float*)d_in[4];
    const float* W3  = (const float*)d_in[5];
    const float* b3  = (const float*)d_in[6];
    const float* cb  = (const float*)d_in[7];
    float* out = (float*)d_out;

    cudaFuncSetAttribute(vq_main, cudaFuncAttributeMaxDynamicSharedMemorySize,
                         SMEM_FLOATS * (int)sizeof(float));

    vq_main<<<NBLOCKS, NTHREADS, SMEM_FLOATS * sizeof(float)>>>(
        obs, W1, b1, W2, b2, W3, b3, cb, out);
}

// round 12
// speedup vs baseline: 1.0727x; 1.0727x over previous
#include <cuda_runtime.h>
#include <cuda_fp16.h>
#include <math.h>
#include <float.h>
#include <stdint.h>

// ---------------- problem constants ----------------
#define TOKENS_TOTAL (32*2048)
#define IN_DIM   128
#define HID      64
#define OUT_DIM  64
#define CODEBOOK 2048

#define TB       256
#define NTHREADS 512
#define NBLOCKS  (TOKENS_TOTAL/TB)     // 256
#define XT_STRIDE 258
#define CCH      64
#define NCH      (CODEBOOK/CCH)        // 32

// output layout: msg ++ idx(as float) ++ loss
#define MSG_ELEMS ((size_t)TOKENS_TOTAL*OUT_DIM)
#define IDX_OFF   MSG_ELEMS
#define LOSS_OFF  (MSG_ELEMS + TOKENS_TOTAL)

// ---------------- smem layout (word offsets) ----------------
#define OFF_E2   0                      // 2048 f
#define OFF_XT   2048                   // 64 x 258 = 16512 -> 18560
#define OFF_B    18560                  // 3 bufs x 4608 = 13824 -> 32384
#define B_ROW_W   36
#define B_TILE_W  (CCH*B_ROW_W)         // 2304
#define B_BUF_W   (2*B_TILE_W)          // 4608 (hi then lo)
// MLP-phase overlays (time-disjoint)
#define OFF_W    18560                  // weights (<= 8192 f), MLP only
#define OFF_OBS  26752                  // obs half-tile / h2 (16384 f) -> 43136, MLP only
#define OFF_H1   2048                   // h1 (16384 f) inside XT region (XT written later)
#define SMEM_FLOATS 43136               // 172544 B ; 1 CTA/SM

// packed codebook, FRAGMENT ORDER (r5-verified): [hi | lo] tiles,
// each [2048 codes][32 words], packed[c][q*8 + kb*2 + b] = orig word kb*8 + 4b + q
#define CBW 32
__device__ uint4 g_cbpack4[2 * CODEBOOK * CBW / 4];   // 512 KB
__device__ float g_e2[CODEBOOK];
__device__ float g_partial[NBLOCKS];
__device__ int   g_done = 0;

// ---------------- fp16 split helpers ----------------
__device__ __forceinline__ void split_h2(float x0, float x1, uint32_t& h, uint32_t& l) {
    __half h0 = __float2half_rn(x0);
    __half h1 = __float2half_rn(x1);
    float  l0 = x0 - __half2float(h0);
    float  l1 = x1 - __half2float(h1);
    __half2 hh = __halves2half2(h0, h1);
    __half2 ll = __floats2half2_rn(l0, l1);
    h = *(uint32_t*)&hh;
    l = *(uint32_t*)&ll;
}

__device__ __forceinline__ void mma16(float* c, const uint32_t* a, uint32_t b0, uint32_t b1) {
    asm volatile(
        "mma.sync.aligned.m16n8k16.row.col.f32.f16.f16.f32 "
        "{%0,%1,%2,%3}, {%4,%5,%6,%7}, {%8,%9}, {%0,%1,%2,%3};"
        : "+f"(c[0]), "+f"(c[1]), "+f"(c[2]), "+f"(c[3])
        : "r"(a[0]), "r"(a[1]), "r"(a[2]), "r"(a[3]), "r"(b0), "r"(b1));
}

// packed fp32x2 (MLP)
__device__ __forceinline__ unsigned long long dup2(float x) {
    unsigned long long r; asm("mov.b64 %0, {%1, %1};" : "=l"(r) : "f"(x)); return r;
}
__device__ __forceinline__ void ffma2(unsigned long long& d, unsigned long long a, unsigned long long b) {
    asm("fma.rn.f32x2 %0, %1, %2, %0;" : "+l"(d) : "l"(a), "l"(b));
}
__device__ __forceinline__ float lo32(unsigned long long v) { return __uint_as_float((unsigned)v); }
__device__ __forceinline__ float hi32(unsigned long long v) { return __uint_as_float((unsigned)(v >> 32)); }

// ---------------- MLP layer (per-token accumulation order identical to rounds 1..11) ----------------
template<int KD, int NT, int OUTMODE, bool RELU>
__device__ __forceinline__ void mlp_layer(const float* in_s, int in_stride,
                                          const float* w_s, const float* __restrict__ b_g,
                                          float* out_s, int tid)
{
    const int jg = tid & 7;
    const int tg = tid >> 3;             // 0..63 with 512 threads
    float bj[4][2];
#pragma unroll
    for (int jj = 0; jj < 4; jj++) {
        int j0 = jg*2 + 16*jj;
        bj[jj][0] = __ldg(b_g + j0);
        bj[jj][1] = __ldg(b_g + j0 + 1);
    }
    unsigned long long acc[NT][4];
#pragma unroll
    for (int it = 0; it < NT; it++)
#pragma unroll
        for (int jj = 0; jj < 4; jj++) acc[it][jj] = 0ULL;

#pragma unroll 4
    for (int k0 = 0; k0 < KD; k0 += 4) {
        float xin[NT][4];
#pragma unroll
        for (int it = 0; it < NT; it++) {
            float4 v = *(const float4*)(in_s + (tg*NT + it)*in_stride + k0);
            xin[it][0] = v.x; xin[it][1] = v.y; xin[it][2] = v.z; xin[it][3] = v.w;
        }
#pragma unroll
        for (int kk = 0; kk < 4; kk++) {
            unsigned long long wp[4];
#pragma unroll
            for (int jj = 0; jj < 4; jj++)
                wp[jj] = *(const unsigned long long*)(w_s + (k0+kk)*64 + jg*2 + 16*jj);
#pragma unroll
            for (int it = 0; it < NT; it++) {
                unsigned long long xd = dup2(xin[it][kk]);
#pragma unroll
                for (int jj = 0; jj < 4; jj++) ffma2(acc[it][jj], xd, wp[jj]);
            }
        }
    }
#pragma unroll
    for (int it = 0; it < NT; it++) {
        int t = tg*NT + it;
#pragma unroll
        for (int jj = 0; jj < 4; jj++) {
            int j0 = jg*2 + 16*jj;
            float v0 = lo32(acc[it][jj]) + bj[jj][0];
            float v1 = hi32(acc[it][jj]) + bj[jj][1];
            if (RELU) { v0 = fmaxf(v0, 0.0f); v1 = fmaxf(v1, 0.0f); }
            if (OUTMODE == 0) {
                out_s[t*64 + j0]     = v0;
                out_s[t*64 + j0 + 1] = v1;
            } else {
                out_s[j0*XT_STRIDE + t]       = v0;
                out_s[(j0 + 1)*XT_STRIDE + t] = v1;
            }
        }
    }
}

// ---------------- prep: fragment-order fp16 hi/lo pack + exact e2 (r5/r10-verified) ----------------
__global__ void prep_kernel(const float* __restrict__ cb) {
    int gt = blockIdx.x * 256 + threadIdx.x;
    int c  = gt >> 2;
    int q  = gt & 3;
    if (c >= CODEBOOK) return;

    uint32_t hw[8], lw[8];
    float sq = 0.0f;
#pragma unroll
    for (int s = 0; s < 8; s++) {
        int kb = s >> 1, b = s & 1;
        int w  = kb*8 + 4*b + q;
        float x0 = __ldg(cb + (size_t)c*OUT_DIM + 2*w);
        float x1 = __ldg(cb + (size_t)c*OUT_DIM + 2*w + 1);
        split_h2(x0, x1, hw[s], lw[s]);
        sq += x0*x0 + x1*x1;
    }
    uint32_t* pack = (uint32_t*)g_cbpack4;
    uint32_t* hrow = pack + c*CBW + q*8;
    uint32_t* lrow = hrow + CODEBOOK*CBW;
    *(uint4*)(hrow)     = make_uint4(hw[0], hw[1], hw[2], hw[3]);
    *(uint4*)(hrow + 4) = make_uint4(hw[4], hw[5], hw[6], hw[7]);
    *(uint4*)(lrow)     = make_uint4(lw[0], lw[1], lw[2], lw[3]);
    *(uint4*)(lrow + 4) = make_uint4(lw[4], lw[5], lw[6], lw[7]);

    sq += __shfl_xor_sync(0xffffffffu, sq, 1);
    sq += __shfl_xor_sync(0xffffffffu, sq, 2);
    if (q == 0) g_e2[c] = sq;
}

// ---------------- staging: pure uint4 copy (512 threads, 1 hi + 1 lo each) ----------------
__device__ __forceinline__ void b_ldg(int ch, int tid, uint4* v) {
    const uint4* hb = g_cbpack4 + (size_t)ch*CCH*(CBW/4);   // 512 uint4 hi
    const uint4* lb = hb + CODEBOOK*(CBW/4);
    v[0] = __ldg(hb + tid);
    v[1] = __ldg(lb + tid);
}
__device__ __forceinline__ void b_sts(uint32_t* bbuf, int tid, const uint4* v) {
    int c0 = tid >> 3, sub = tid & 7;
    *(uint4*)(bbuf + c0*B_ROW_W + sub*4)            = v[0];
    *(uint4*)(bbuf + B_TILE_W + c0*B_ROW_W + sub*4) = v[1];
}

// ---------------- fused main kernel ----------------
__global__ void __launch_bounds__(NTHREADS, 1)
vq_main(const float* __restrict__ obs,
        const float* __restrict__ W1, const float* __restrict__ b1,
        const float* __restrict__ W2, const float* __restrict__ b2,
        const float* __restrict__ W3, const float* __restrict__ b3,
        const float* __restrict__ cb,
        float* __restrict__ out)
{
    extern __shared__ float sm[];
    const int tid  = threadIdx.x;
    const int wid  = tid >> 5;           // 0..15
    const int lane = tid & 31;
    const int r    = lane >> 2;
    const int q    = lane & 3;
    const int tok0 = blockIdx.x * TB;

    for (int i = tid; i < CODEBOOK; i += NTHREADS) sm[OFF_E2 + i] = g_e2[i];

    // ================= MLP (FFMA2; per-token order identical to prior rounds) =================
    {
        const float4* w4 = (const float4*)W1;
        float4* d4 = (float4*)(sm + OFF_W);
        for (int i = tid; i < (IN_DIM*HID)/4; i += NTHREADS) d4[i] = w4[i];
    }
    for (int half = 0; half < 2; half++) {
        __syncthreads();
        const float4* o4 = (const float4*)(obs + (size_t)(tok0 + half*128) * IN_DIM);
        float4* d4 = (float4*)(sm + OFF_OBS);
        for (int i = tid; i < (128*IN_DIM)/4; i += NTHREADS) d4[i] = o4[i];
        __syncthreads();
        mlp_layer<IN_DIM, 2, 0, true>(sm + OFF_OBS, IN_DIM, sm + OFF_W, b1,
                                      sm + OFF_H1 + half*128*HID, tid);
    }
    __syncthreads();
    {
        const float4* w4 = (const float4*)W2;
        float4* d4 = (float4*)(sm + OFF_W);
        for (int i = tid; i < (HID*HID)/4; i += NTHREADS) d4[i] = w4[i];
    }
    __syncthreads();
    mlp_layer<HID, 4, 0, true>(sm + OFF_H1, HID, sm + OFF_W, b2, sm + OFF_OBS, tid);
    __syncthreads();
    {
        const float4* w4 = (const float4*)W3;
        float4* d4 = (float4*)(sm + OFF_W);
        for (int i = tid; i < (HID*OUT_DIM)/4; i += NTHREADS) d4[i] = w4[i];
    }
    __syncthreads();
    mlp_layer<HID, 4, 1, false>(sm + OFF_OBS, HID, sm + OFF_W, b3, sm + OFF_XT, tid);
    __syncthreads();

    // ========== A fragments (m16 x k64, fp16 hi/lo), one m16 tile per warp ==========
    const float* xsT = sm + OFF_XT;
    const int tokw = wid * 16;
    uint32_t Ah[4][4], Al[4][4];
#pragma unroll
    for (int kb = 0; kb < 4; kb++) {
        int k0 = kb*16;
        const float* x0 = xsT + tokw;
        float v00 = x0[(k0 + 2*q    )*XT_STRIDE + r];
        float v01 = x0[(k0 + 2*q + 1)*XT_STRIDE + r];
        float v10 = x0[(k0 + 2*q    )*XT_STRIDE + r + 8];
        float v11 = x0[(k0 + 2*q + 1)*XT_STRIDE + r + 8];
        float v20 = x0[(k0 + 2*q + 8)*XT_STRIDE + r];
        float v21 = x0[(k0 + 2*q + 9)*XT_STRIDE + r];
        float v30 = x0[(k0 + 2*q + 8)*XT_STRIDE + r + 8];
        float v31 = x0[(k0 + 2*q + 9)*XT_STRIDE + r + 8];
        split_h2(v00, v01, Ah[kb][0], Al[kb][0]);
        split_h2(v10, v11, Ah[kb][1], Al[kb][1]);
        split_h2(v20, v21, Ah[kb][2], Al[kb][2]);
        split_h2(v30, v31, Ah[kb][3], Al[kb][3]);
    }

    // ================= VQ: fp16 m16n8k16 3-term, triple buffer =================
    float best_d0 = FLT_MAX, best_d1 = FLT_MAX;
    int   best_c0 = 0,       best_c1 = 0;

    uint32_t* bw = (uint32_t*)(sm + OFF_B);

    {   // prologue: stage chunk 0
        uint4 st[2];
        b_ldg(0, tid, st);
        b_sts(bw, tid, st);
        __syncthreads();
    }

    for (int ch = 0; ch < NCH; ch++) {
        const int buf = ch % 3;
        uint4 pv[2];
        const bool more = (ch + 1 < NCH);
        if (more) b_ldg(ch + 1, tid, pv);

        const uint32_t* bb = bw + buf*B_BUF_W;

#pragma unroll
        for (int grp = 0; grp < 2; grp++) {
#pragma unroll
            for (int gp = 0; gp < 2; gp++) {
                const uint32_t* pa = bb + (grp*32 + gp*16 + r)*B_ROW_W + q*8;
                const uint32_t* pb = pa + 8*B_ROW_W;
                uint4 h0a = *(const uint4*)(pa);
                uint4 h1a = *(const uint4*)(pa + 4);
                uint4 h0b = *(const uint4*)(pb);
                uint4 h1b = *(const uint4*)(pb + 4);
                uint4 l0a = *(const uint4*)(pa + B_TILE_W);
                uint4 l1a = *(const uint4*)(pa + B_TILE_W + 4);
                uint4 l0b = *(const uint4*)(pb + B_TILE_W);
                uint4 l1b = *(const uint4*)(pb + B_TILE_W + 4);

                float aMa[4]={0,0,0,0}, aMb[4]={0,0,0,0};
                float aCa[4]={0,0,0,0}, aCb[4]={0,0,0,0};
                float aDa[4]={0,0,0,0}, aDb[4]={0,0,0,0};

                mma16(aMa, Ah[0], h0a.x, h0a.y);  mma16(aMb, Ah[0], h0b.x, h0b.y);
                mma16(aCa, Ah[0], l0a.x, l0a.y);  mma16(aCb, Ah[0], l0b.x, l0b.y);
                mma16(aDa, Al[0], h0a.x, h0a.y);  mma16(aDb, Al[0], h0b.x, h0b.y);

                mma16(aMa, Ah[1], h0a.z, h0a.w);  mma16(aMb, Ah[1], h0b.z, h0b.w);
                mma16(aCa, Ah[1], l0a.z, l0a.w);  mma16(aCb, Ah[1], l0b.z, l0b.w);
                mma16(aDa, Al[1], h0a.z, h0a.w);  mma16(aDb, Al[1], h0b.z, h0b.w);

                mma16(aMa, Ah[2], h1a.x, h1a.y);  mma16(aMb, Ah[2], h1b.x, h1b.y);
                mma16(aCa, Ah[2], l1a.x, l1a.y);  mma16(aCb, Ah[2], l1b.x, l1b.y);
                mma16(aDa, Al[2], h1a.x, h1a.y);  mma16(aDb, Al[2], h1b.x, h1b.y);

                mma16(aMa, Ah[3], h1a.z, h1a.w);  mma16(aMb, Ah[3], h1b.z, h1b.w);
                mma16(aCa, Ah[3], l1a.z, l1a.w);  mma16(aCb, Ah[3], l1b.z, l1b.w);
                mma16(aDa, Al[3], h1a.z, h1a.w);  mma16(aDb, Al[3], h1b.z, h1b.w);

#pragma unroll
                for (int half = 0; half < 2; half++) {
                    const float* aM = half ? aMb : aMa;
                    const float* aC = half ? aCb : aCa;
                    const float* aD = half ? aDb : aDa;
                    int code0 = ch*CCH + grp*32 + (gp*2 + half)*8 + 2*q;
                    float e20 = sm[OFF_E2 + code0];
                    float e21 = sm[OFF_E2 + code0 + 1];
                    float s0 = aM[0] + aC[0] + aD[0];
                    float s1 = aM[1] + aC[1] + aD[1];
                    float s2 = aM[2] + aC[2] + aD[2];
                    float s3 = aM[3] + aC[3] + aD[3];
                    float d0 = fmaf(-2.0f, s0, e20);
                    float d1 = fmaf(-2.0f, s1, e21);
                    float d2 = fmaf(-2.0f, s2, e20);
                    float d3 = fmaf(-2.0f, s3, e21);
                    if (d0 < best_d0) { best_d0 = d0; best_c0 = code0; }
                    if (d1 < best_d0) { best_d0 = d1; best_c0 = code0 + 1; }
                    if (d2 < best_d1) { best_d1 = d2; best_c1 = code0; }
                    if (d3 < best_d1) { best_d1 = d3; best_c1 = code0 + 1; }
                }
            }
        }

        if (more) b_sts(bw + ((ch + 1) % 3)*B_BUF_W, tid, pv);
        __syncthreads();
    }

    // ---- cross-lane argmin, tie-break smaller code ----
#pragma unroll
    for (int m = 1; m <= 2; m <<= 1) {
        float od0 = __shfl_xor_sync(0xffffffffu, best_d0, m);
        int   oc0 = __shfl_xor_sync(0xffffffffu, best_c0, m);
        float od1 = __shfl_xor_sync(0xffffffffu, best_d1, m);
        int   oc1 = __shfl_xor_sync(0xffffffffu, best_c1, m);
        if (od0 < best_d0 || (od0 == best_d0 && oc0 < best_c0)) { best_d0 = od0; best_c0 = oc0; }
        if (od1 < best_d1 || (od1 == best_d1 && oc1 < best_c1)) { best_d1 = od1; best_c1 = oc1; }
    }

    int* sIdx = (int*)sm;                // words 0..256 (E2 no longer needed)
    if (q == 0) {
        int t0 = tokw + r;
        sIdx[t0]     = best_c0;
        sIdx[t0 + 8] = best_c1;
        out[IDX_OFF + (size_t)(tok0 + t0)]     = (float)best_c0;
        out[IDX_OFF + (size_t)(tok0 + t0 + 8)] = (float)best_c1;
    }
    __syncthreads();

    // ---- msg write + commitment-loss partial ----
    float part = 0.0f;
    for (int f = tid; f < TB*OUT_DIM; f += NTHREADS) {
        int t = f >> 6, j = f & 63;
        int c = sIdx[t];
        float qv = __ldg(cb + (size_t)c * OUT_DIM + j);
        float xv = xsT[j*XT_STRIDE + t];
        out[(size_t)(tok0 + t)*OUT_DIM + j] = xv + (qv - xv);
        float dd = qv - xv;
        part += dd * dd;
    }
#pragma unroll
    for (int o = 16; o > 0; o >>= 1)
        part += __shfl_down_sync(0xffffffffu, part, o);
    __shared__ float swred[16];
    __shared__ int isLast;
    if ((tid & 31) == 0) swred[tid >> 5] = part;
    __syncthreads();
    if (tid == 0) {
        float s = 0.0f;
#pragma unroll
        for (int w = 0; w < 16; w++) s += swred[w];
        g_partial[blockIdx.x] = s;
        __threadfence();
        isLast = (atomicAdd(&g_done, 1) == NBLOCKS - 1);
    }
    __syncthreads();

    // ---- last block: deterministic loss reduction ----
    if (isLast) {
        volatile float* gp = g_partial;
        float* red = sm + 512;
        if (tid < NBLOCKS) red[tid] = gp[tid];
        __syncthreads();
        for (int o = NBLOCKS/2; o > 0; o >>= 1) {
            if (tid < o) red[tid] += red[tid + o];
            __syncthreads();
        }
        if (tid == 0) {
            out[LOSS_OFF] = red[0] * (1.0f / (float)MSG_ELEMS);
            g_done = 0;   // reset for next graph replay
        }
    }
}

extern "C" void kernel_launch(void* const* d_in, const int* in_sizes, int n_in,
                              void* d_out, int out_size)
{
    const float* obs = (const float*)d_in[0];
    const float* W1  = (const float*)d_in[1];
    const float* b1  = (const float*)d_in[2];
    const float* W2  = (const float*)d_in[3];
    const float* b2  = (const float*)d_in[4];
    const float* W3  = (const float*)d_in[5];
    const float* b3  = (const float*)d_in[6];
    const float* cb  = (const float*)d_in[7];
    float* out = (float*)d_out;

    cudaFuncSetAttribute(vq_main, cudaFuncAttributeMaxDynamicSharedMemorySize,
                         SMEM_FLOATS * (int)sizeof(float));

    prep_kernel<<<(CODEBOOK*4 + 255)/256, 256>>>(cb);
    vq_main<<<NBLOCKS, NTHREADS, SMEM_FLOATS * sizeof(float)>>>(
        obs, W1, b1, W2, b2, W3, b3, cb, out);
}

// round 13
// speedup vs baseline: 1.1114x; 1.0361x over previous
#include <cuda_runtime.h>
#include <cuda_fp16.h>
#include <math.h>
#include <float.h>
#include <stdint.h>

// ---------------- problem constants ----------------
#define TOKENS_TOTAL (32*2048)
#define IN_DIM   128
#define HID      64
#define OUT_DIM  64
#define CODEBOOK 2048

#define TB       128
#define NTHREADS 256
#define NBLOCKS  (TOKENS_TOTAL/TB)     // 512
#define XT_STRIDE 130
#define CCH      64
#define NCH      (CODEBOOK/CCH)        // 32

// output layout: msg ++ idx(as float) ++ loss
#define MSG_ELEMS ((size_t)TOKENS_TOTAL*OUT_DIM)
#define IDX_OFF   MSG_ELEMS
#define LOSS_OFF  (MSG_ELEMS + TOKENS_TOTAL)

// ---------------- smem layout (word offsets) ----------------
#define OFF_E2   0                      // 2048 f
#define OFF_XT   2048                   // 64 x 130 f -> end 10368
#define OFF_B    10368                  // 3 bufs x (hi 64x36 + lo 64x36) = 13824 w -> 24192
#define B_ROW_W   36
#define B_TILE_W  (CCH*B_ROW_W)         // 2304
#define B_BUF_W   (2*B_TILE_W)          // 4608
// MLP-phase overlays (time-disjoint)
#define OFF_W    10368
#define OFF_OBS  18560                  // -> 26752
#define OFF_H1   2048
#define SMEM_FLOATS 26752               // 107008 B ; x2 CTAs fits

// packed codebook, FRAGMENT ORDER (r5/r10-verified)
#define CBW 32
__device__ uint4 g_cbpack4[2 * CODEBOOK * CBW / 4];
__device__ float g_e2[CODEBOOK];
__device__ float g_partial[NBLOCKS];
__device__ int   g_done = 0;

// ---------------- fp16 split helpers ----------------
__device__ __forceinline__ void split_h2(float x0, float x1, uint32_t& h, uint32_t& l) {
    __half h0 = __float2half_rn(x0);
    __half h1 = __float2half_rn(x1);
    float  l0 = x0 - __half2float(h0);
    float  l1 = x1 - __half2float(h1);
    __half2 hh = __halves2half2(h0, h1);
    __half2 ll = __floats2half2_rn(l0, l1);
    h = *(uint32_t*)&hh;
    l = *(uint32_t*)&ll;
}

__device__ __forceinline__ void mma16(float* c, const uint32_t* a, uint32_t b0, uint32_t b1) {
    asm volatile(
        "mma.sync.aligned.m16n8k16.row.col.f32.f16.f16.f32 "
        "{%0,%1,%2,%3}, {%4,%5,%6,%7}, {%8,%9}, {%0,%1,%2,%3};"
        : "+f"(c[0]), "+f"(c[1]), "+f"(c[2]), "+f"(c[3])
        : "r"(a[0]), "r"(a[1]), "r"(a[2]), "r"(a[3]), "r"(b0), "r"(b1));
}

// packed fp32x2 (MLP)
__device__ __forceinline__ unsigned long long dup2(float x) {
    unsigned long long r; asm("mov.b64 %0, {%1, %1};" : "=l"(r) : "f"(x)); return r;
}
__device__ __forceinline__ void ffma2(unsigned long long& d, unsigned long long a, unsigned long long b) {
    asm("fma.rn.f32x2 %0, %1, %2, %0;" : "+l"(d) : "l"(a), "l"(b));
}
__device__ __forceinline__ float lo32(unsigned long long v) { return __uint_as_float((unsigned)v); }
__device__ __forceinline__ float hi32(unsigned long long v) { return __uint_as_float((unsigned)(v >> 32)); }

// ---------------- MLP layer (proven rounds 1..12) ----------------
template<int KD, int NT, int OUTMODE, bool RELU>
__device__ __forceinline__ void mlp_layer(const float* in_s, int in_stride,
                                          const float* w_s, const float* __restrict__ b_g,
                                          float* out_s, int tid)
{
    const int jg = tid & 7;
    const int tg = tid >> 3;
    float bj[4][2];
#pragma unroll
    for (int jj = 0; jj < 4; jj++) {
        int j0 = jg*2 + 16*jj;
        bj[jj][0] = __ldg(b_g + j0);
        bj[jj][1] = __ldg(b_g + j0 + 1);
    }
    unsigned long long acc[NT][4];
#pragma unroll
    for (int it = 0; it < NT; it++)
#pragma unroll
        for (int jj = 0; jj < 4; jj++) acc[it][jj] = 0ULL;

#pragma unroll 4
    for (int k0 = 0; k0 < KD; k0 += 4) {
        float xin[NT][4];
#pragma unroll
        for (int it = 0; it < NT; it++) {
            float4 v = *(const float4*)(in_s + (tg*NT + it)*in_stride + k0);
            xin[it][0] = v.x; xin[it][1] = v.y; xin[it][2] = v.z; xin[it][3] = v.w;
        }
#pragma unroll
        for (int kk = 0; kk < 4; kk++) {
            unsigned long long wp[4];
#pragma unroll
            for (int jj = 0; jj < 4; jj++)
                wp[jj] = *(const unsigned long long*)(w_s + (k0+kk)*64 + jg*2 + 16*jj);
#pragma unroll
            for (int it = 0; it < NT; it++) {
                unsigned long long xd = dup2(xin[it][kk]);
#pragma unroll
                for (int jj = 0; jj < 4; jj++) ffma2(acc[it][jj], xd, wp[jj]);
            }
        }
    }
#pragma unroll
    for (int it = 0; it < NT; it++) {
        int t = tg*NT + it;
#pragma unroll
        for (int jj = 0; jj < 4; jj++) {
            int j0 = jg*2 + 16*jj;
            float v0 = lo32(acc[it][jj]) + bj[jj][0];
            float v1 = hi32(acc[it][jj]) + bj[jj][1];
            if (RELU) { v0 = fmaxf(v0, 0.0f); v1 = fmaxf(v1, 0.0f); }
            if (OUTMODE == 0) {
                out_s[t*64 + j0]     = v0;
                out_s[t*64 + j0 + 1] = v1;
            } else {
                out_s[j0*XT_STRIDE + t]       = v0;
                out_s[(j0 + 1)*XT_STRIDE + t] = v1;
            }
        }
    }
}

// ---------------- prep: fragment-order fp16 hi/lo pack + exact e2 ----------------
__global__ void prep_kernel(const float* __restrict__ cb) {
    int gt = blockIdx.x * 256 + threadIdx.x;
    int c  = gt >> 2;
    int q  = gt & 3;
    if (c >= CODEBOOK) return;

    uint32_t hw[8], lw[8];
    float sq = 0.0f;
#pragma unroll
    for (int s = 0; s < 8; s++) {
        int kb = s >> 1, b = s & 1;
        int w  = kb*8 + 4*b + q;
        float x0 = __ldg(cb + (size_t)c*OUT_DIM + 2*w);
        float x1 = __ldg(cb + (size_t)c*OUT_DIM + 2*w + 1);
        split_h2(x0, x1, hw[s], lw[s]);
        sq += x0*x0 + x1*x1;
    }
    uint32_t* pack = (uint32_t*)g_cbpack4;
    uint32_t* hrow = pack + c*CBW + q*8;
    uint32_t* lrow = hrow + CODEBOOK*CBW;
    *(uint4*)(hrow)     = make_uint4(hw[0], hw[1], hw[2], hw[3]);
    *(uint4*)(hrow + 4) = make_uint4(hw[4], hw[5], hw[6], hw[7]);
    *(uint4*)(lrow)     = make_uint4(lw[0], lw[1], lw[2], lw[3]);
    *(uint4*)(lrow + 4) = make_uint4(lw[4], lw[5], lw[6], lw[7]);

    sq += __shfl_xor_sync(0xffffffffu, sq, 1);
    sq += __shfl_xor_sync(0xffffffffu, sq, 2);
    if (q == 0) g_e2[c] = sq;
}

// ---------------- staging: pure uint4 copy ----------------
__device__ __forceinline__ void b_ldg(int ch, int tid, uint4* v) {
    const uint4* hb = g_cbpack4 + (size_t)ch*CCH*(CBW/4);
    const uint4* lb = hb + CODEBOOK*(CBW/4);
    v[0] = __ldg(hb + tid);
    v[1] = __ldg(hb + tid + 256);
    v[2] = __ldg(lb + tid);
    v[3] = __ldg(lb + tid + 256);
}
__device__ __forceinline__ void b_sts(uint32_t* bbuf, int tid, const uint4* v) {
#pragma unroll
    for (int i = 0; i < 2; i++) {
        int idx = tid + i*256;
        int c0 = idx >> 3, sub = idx & 7;
        *(uint4*)(bbuf + c0*B_ROW_W + sub*4)            = v[i];
        *(uint4*)(bbuf + B_TILE_W + c0*B_ROW_W + sub*4) = v[i+2];
    }
}

// ---------------- fused kernel ----------------
__global__ void __launch_bounds__(NTHREADS, 2)
vq_main(const float* __restrict__ obs,
        const float* __restrict__ W1, const float* __restrict__ b1,
        const float* __restrict__ W2, const float* __restrict__ b2,
        const float* __restrict__ W3, const float* __restrict__ b3,
        const float* __restrict__ cb,
        float* __restrict__ out)
{
    extern __shared__ float sm[];
    const int tid  = threadIdx.x;
    const int wid  = tid >> 5;
    const int lane = tid & 31;
    const int r    = lane >> 2;
    const int q    = lane & 3;
    const int tok0 = blockIdx.x * TB;

    for (int i = tid; i < CODEBOOK; i += NTHREADS) sm[OFF_E2 + i] = g_e2[i];

    // ================= MLP =================
    {
        const float4* w4 = (const float4*)W1;
        float4* d4 = (float4*)(sm + OFF_W);
        for (int i = tid; i < (IN_DIM*HID)/4; i += NTHREADS) d4[i] = w4[i];
    }
    for (int half = 0; half < 2; half++) {
        __syncthreads();
        const float4* o4 = (const float4*)(obs + (size_t)(tok0 + half*64) * IN_DIM);
        float4* d4 = (float4*)(sm + OFF_OBS);
        for (int i = tid; i < (64*IN_DIM)/4; i += NTHREADS) d4[i] = o4[i];
        __syncthreads();
        mlp_layer<IN_DIM, 2, 0, true>(sm + OFF_OBS, IN_DIM, sm + OFF_W, b1,
                                      sm + OFF_H1 + half*64*HID, tid);
    }
    __syncthreads();
    {
        const float4* w4 = (const float4*)W2;
        float4* d4 = (float4*)(sm + OFF_W);
        for (int i = tid; i < (HID*HID)/4; i += NTHREADS) d4[i] = w4[i];
    }
    __syncthreads();
    mlp_layer<HID, 4, 0, true>(sm + OFF_H1, HID, sm + OFF_W, b2, sm + OFF_OBS, tid);
    __syncthreads();
    {
        const float4* w4 = (const float4*)W3;
        float4* d4 = (float4*)(sm + OFF_W);
        for (int i = tid; i < (HID*OUT_DIM)/4; i += NTHREADS) d4[i] = w4[i];
    }
    __syncthreads();
    mlp_layer<HID, 4, 1, false>(sm + OFF_OBS, HID, sm + OFF_W, b3, sm + OFF_XT, tid);
    __syncthreads();

    // ========== A fragments ==========
    const float* xsT = sm + OFF_XT;
    const int tokw = wid * 16;
    uint32_t Ah[4][4], Al[4][4];
#pragma unroll
    for (int kb = 0; kb < 4; kb++) {
        int k0 = kb*16;
        const float* x0 = xsT + tokw;
        float v00 = x0[(k0 + 2*q    )*XT_STRIDE + r];
        float v01 = x0[(k0 + 2*q + 1)*XT_STRIDE + r];
        float v10 = x0[(k0 + 2*q    )*XT_STRIDE + r + 8];
        float v11 = x0[(k0 + 2*q + 1)*XT_STRIDE + r + 8];
        float v20 = x0[(k0 + 2*q + 8)*XT_STRIDE + r];
        float v21 = x0[(k0 + 2*q + 9)*XT_STRIDE + r];
        float v30 = x0[(k0 + 2*q + 8)*XT_STRIDE + r + 8];
        float v31 = x0[(k0 + 2*q + 9)*XT_STRIDE + r + 8];
        split_h2(v00, v01, Ah[kb][0], Al[kb][0]);
        split_h2(v10, v11, Ah[kb][1], Al[kb][1]);
        split_h2(v20, v21, Ah[kb][2], Al[kb][2]);
        split_h2(v30, v31, Ah[kb][3], Al[kb][3]);
    }

    // ================= VQ: merged 3-term chains (single accumulator per code-row) =================
    float best_d0 = FLT_MAX, best_d1 = FLT_MAX;
    int   best_c0 = 0,       best_c1 = 0;

    uint32_t* bw = (uint32_t*)(sm + OFF_B);

    {
        uint4 st[4];
        b_ldg(0, tid, st);
        b_sts(bw, tid, st);
        __syncthreads();
    }

    for (int ch = 0; ch < NCH; ch++) {
        const int buf = ch % 3;
        uint4 pv[4];
        const bool more = (ch + 1 < NCH);
        if (more) b_ldg(ch + 1, tid, pv);

        const uint32_t* bb = bw + buf*B_BUF_W;

#pragma unroll
        for (int grp = 0; grp < 2; grp++) {
#pragma unroll
            for (int gp = 0; gp < 2; gp++) {
                const uint32_t* pa = bb + (grp*32 + gp*16 + r)*B_ROW_W + q*8;
                const uint32_t* pb = pa + 8*B_ROW_W;
                uint4 h0a = *(const uint4*)(pa);
                uint4 h1a = *(const uint4*)(pa + 4);
                uint4 h0b = *(const uint4*)(pb);
                uint4 h1b = *(const uint4*)(pb + 4);
                uint4 l0a = *(const uint4*)(pa + B_TILE_W);
                uint4 l1a = *(const uint4*)(pa + B_TILE_W + 4);
                uint4 l0b = *(const uint4*)(pb + B_TILE_W);
                uint4 l1b = *(const uint4*)(pb + B_TILE_W + 4);

                float aa[4]={0,0,0,0}, ab[4]={0,0,0,0};

                // kb0 (words .x,.y): hh, hl, lh -> one accumulator per row
                mma16(aa, Ah[0], h0a.x, h0a.y);  mma16(ab, Ah[0], h0b.x, h0b.y);
                mma16(aa, Ah[0], l0a.x, l0a.y);  mma16(ab, Ah[0], l0b.x, l0b.y);
                mma16(aa, Al[0], h0a.x, h0a.y);  mma16(ab, Al[0], h0b.x, h0b.y);
                // kb1 (words .z,.w)
                mma16(aa, Ah[1], h0a.z, h0a.w);  mma16(ab, Ah[1], h0b.z, h0b.w);
                mma16(aa, Ah[1], l0a.z, l0a.w);  mma16(ab, Ah[1], l0b.z, l0b.w);
                mma16(aa, Al[1], h0a.z, h0a.w);  mma16(ab, Al[1], h0b.z, h0b.w);
                // kb2
                mma16(aa, Ah[2], h1a.x, h1a.y);  mma16(ab, Ah[2], h1b.x, h1b.y);
                mma16(aa, Ah[2], l1a.x, l1a.y);  mma16(ab, Ah[2], l1b.x, l1b.y);
                mma16(aa, Al[2], h1a.x, h1a.y);  mma16(ab, Al[2], h1b.x, h1b.y);
                // kb3
                mma16(aa, Ah[3], h1a.z, h1a.w);  mma16(ab, Ah[3], h1b.z, h1b.w);
                mma16(aa, Ah[3], l1a.z, l1a.w);  mma16(ab, Ah[3], l1b.z, l1b.w);
                mma16(aa, Al[3], h1a.z, h1a.w);  mma16(ab, Al[3], h1b.z, h1b.w);

#pragma unroll
                for (int half = 0; half < 2; half++) {
                    const float* ac = half ? ab : aa;
                    int code0 = ch*CCH + grp*32 + (gp*2 + half)*8 + 2*q;
                    float e20 = sm[OFF_E2 + code0];
                    float e21 = sm[OFF_E2 + code0 + 1];
                    float d0 = fmaf(-2.0f, ac[0], e20);
                    float d1 = fmaf(-2.0f, ac[1], e21);
                    float d2 = fmaf(-2.0f, ac[2], e20);
                    float d3 = fmaf(-2.0f, ac[3], e21);
                    if (d0 < best_d0) { best_d0 = d0; best_c0 = code0; }
                    if (d1 < best_d0) { best_d0 = d1; best_c0 = code0 + 1; }
                    if (d2 < best_d1) { best_d1 = d2; best_c1 = code0; }
                    if (d3 < best_d1) { best_d1 = d3; best_c1 = code0 + 1; }
                }
            }
        }

        if (more) b_sts(bw + ((ch + 1) % 3)*B_BUF_W, tid, pv);
        __syncthreads();
    }

    // ---- cross-lane argmin, tie-break smaller code ----
#pragma unroll
    for (int m = 1; m <= 2; m <<= 1) {
        float od0 = __shfl_xor_sync(0xffffffffu, best_d0, m);
        int   oc0 = __shfl_xor_sync(0xffffffffu, best_c0, m);
        float od1 = __shfl_xor_sync(0xffffffffu, best_d1, m);
        int   oc1 = __shfl_xor_sync(0xffffffffu, best_c1, m);
        if (od0 < best_d0 || (od0 == best_d0 && oc0 < best_c0)) { best_d0 = od0; best_c0 = oc0; }
        if (od1 < best_d1 || (od1 == best_d1 && oc1 < best_c1)) { best_d1 = od1; best_c1 = oc1; }
    }

    int* sIdx = (int*)(sm + OFF_B);
    if (q == 0) {
        int t0 = tokw + r;
        sIdx[t0]     = best_c0;
        sIdx[t0 + 8] = best_c1;
        out[IDX_OFF + (size_t)(tok0 + t0)]     = (float)best_c0;
        out[IDX_OFF + (size_t)(tok0 + t0 + 8)] = (float)best_c1;
    }
    __syncthreads();

    // ---- msg write + commitment-loss partial ----
    float part = 0.0f;
    for (int f = tid; f < TB*OUT_DIM; f += NTHREADS) {
        int t = f >> 6, j = f & 63;
        int c = sIdx[t];
        float qv = __ldg(cb + (size_t)c * OUT_DIM + j);
        float xv = xsT[j*XT_STRIDE + t];
        out[(size_t)(tok0 + t)*OUT_DIM + j] = xv + (qv - xv);
        float dd = qv - xv;
        part += dd * dd;
    }
#pragma unroll
    for (int o = 16; o > 0; o >>= 1)
        part += __shfl_down_sync(0xffffffffu, part, o);
    __shared__ float swred[8];
    __shared__ int isLast;
    if ((tid & 31) == 0) swred[tid >> 5] = part;
    __syncthreads();
    if (tid == 0) {
        float s = 0.0f;
#pragma unroll
        for (int w = 0; w < 8; w++) s += swred[w];
        g_partial[blockIdx.x] = s;
        __threadfence();
        isLast = (atomicAdd(&g_done, 1) == NBLOCKS - 1);
    }
    __syncthreads();

    // ---- last block: deterministic loss reduction (same tree as r1..r10 loss_reduce) ----
    if (isLast) {
        volatile float* gp = g_partial;
        float* red = sm + 512;               // E2 region, dead
        red[tid] = gp[tid] + gp[tid + NTHREADS];
        __syncthreads();
        for (int o = NTHREADS/2; o > 0; o >>= 1) {
            if (tid < o) red[tid] += red[tid + o];
            __syncthreads();
        }
        if (tid == 0) {
            out[LOSS_OFF] = red[0] * (1.0f / (float)MSG_ELEMS);
            g_done = 0;
        }
    }
}

extern "C" void kernel_launch(void* const* d_in, const int* in_sizes, int n_in,
                              void* d_out, int out_size)
{
    const float* obs = (const float*)d_in[0];
    const float* W1  = (const float*)d_in[1];
    const float* b1  = (const float*)d_in[2];
    const float* W2  = (const float*)d_in[3];
    const float* b2  = (const float*)d_in[4];
    const float* W3  = (const float*)d_in[5];
    const float* b3  = (const float*)d_in[6];
    const float* cb  = (const float*)d_in[7];
    float* out = (float*)d_out;

    cudaFuncSetAttribute(vq_main, cudaFuncAttributeMaxDynamicSharedMemorySize,
                         SMEM_FLOATS * (int)sizeof(float));

    prep_kernel<<<(CODEBOOK*4 + 255)/256, 256>>>(cb);
    vq_main<<<NBLOCKS, NTHREADS, SMEM_FLOATS * sizeof(float)>>>(
        obs, W1, b1, W2, b2, W3, b3, cb, out);
}

// round 14
// speedup vs baseline: 1.2087x; 1.0875x over previous
#include <cuda_runtime.h>
#include <cuda_fp16.h>
#include <math.h>
#include <float.h>
#include <stdint.h>

// ---------------- problem constants ----------------
#define TOKENS_TOTAL (32*2048)
#define IN_DIM   128
#define HID      64
#define OUT_DIM  64
#define CODEBOOK 2048

#define TB       128
#define NTHREADS 256
#define NBLOCKS  (TOKENS_TOTAL/TB)     // 512
#define XT_STRIDE 130
#define CCH      64
#define NCH      (CODEBOOK/CCH)        // 32

// output layout: msg ++ idx(as float) ++ loss
#define MSG_ELEMS ((size_t)TOKENS_TOTAL*OUT_DIM)
#define IDX_OFF   MSG_ELEMS
#define LOSS_OFF  (MSG_ELEMS + TOKENS_TOTAL)

// ---------------- smem layout (word offsets) ----------------
#define OFF_E2   0                      // 2048 f
#define OFF_XT   2048                   // 64 x 130 f -> end 10368
#define OFF_B    10368                  // 3 bufs x (hi 64x36 + lo 64x36) = 13824 w -> 24192
#define B_ROW_W   36
#define B_TILE_W  (CCH*B_ROW_W)         // 2304
#define B_BUF_W   (2*B_TILE_W)          // 4608
// MLP-phase overlays (time-disjoint)
#define OFF_W    10368
#define OFF_OBS  18560                  // -> 26752
#define OFF_H1   2048
#define SMEM_FLOATS 26752               // 107008 B ; x2 CTAs fits

// packed codebook, FRAGMENT ORDER (r5/r10-verified)
#define CBW 32
__device__ uint4 g_cbpack4[2 * CODEBOOK * CBW / 4];
__device__ float g_e2[CODEBOOK];
__device__ float g_partial[NBLOCKS];
__device__ int   g_done = 0;

// ---------------- fp16 split helpers ----------------
__device__ __forceinline__ void split_h2(float x0, float x1, uint32_t& h, uint32_t& l) {
    __half h0 = __float2half_rn(x0);
    __half h1 = __float2half_rn(x1);
    float  l0 = x0 - __half2float(h0);
    float  l1 = x1 - __half2float(h1);
    __half2 hh = __halves2half2(h0, h1);
    __half2 ll = __floats2half2_rn(l0, l1);
    h = *(uint32_t*)&hh;
    l = *(uint32_t*)&ll;
}

__device__ __forceinline__ void mma16(float* c, const uint32_t* a, uint32_t b0, uint32_t b1) {
    asm volatile(
        "mma.sync.aligned.m16n8k16.row.col.f32.f16.f16.f32 "
        "{%0,%1,%2,%3}, {%4,%5,%6,%7}, {%8,%9}, {%0,%1,%2,%3};"
        : "+f"(c[0]), "+f"(c[1]), "+f"(c[2]), "+f"(c[3])
        : "r"(a[0]), "r"(a[1]), "r"(a[2]), "r"(a[3]), "r"(b0), "r"(b1));
}

// packed fp32x2 (MLP)
__device__ __forceinline__ unsigned long long dup2(float x) {
    unsigned long long r; asm("mov.b64 %0, {%1, %1};" : "=l"(r) : "f"(x)); return r;
}
__device__ __forceinline__ void ffma2(unsigned long long& d, unsigned long long a, unsigned long long b) {
    asm("fma.rn.f32x2 %0, %1, %2, %0;" : "+l"(d) : "l"(a), "l"(b));
}
__device__ __forceinline__ float lo32(unsigned long long v) { return __uint_as_float((unsigned)v); }
__device__ __forceinline__ float hi32(unsigned long long v) { return __uint_as_float((unsigned)(v >> 32)); }

// ---------------- MLP layer (proven rounds 1..13) ----------------
template<int KD, int NT, int OUTMODE, bool RELU>
__device__ __forceinline__ void mlp_layer(const float* in_s, int in_stride,
                                          const float* w_s, const float* __restrict__ b_g,
                                          float* out_s, int tid)
{
    const int jg = tid & 7;
    const int tg = tid >> 3;
    float bj[4][2];
#pragma unroll
    for (int jj = 0; jj < 4; jj++) {
        int j0 = jg*2 + 16*jj;
        bj[jj][0] = __ldg(b_g + j0);
        bj[jj][1] = __ldg(b_g + j0 + 1);
    }
    unsigned long long acc[NT][4];
#pragma unroll
    for (int it = 0; it < NT; it++)
#pragma unroll
        for (int jj = 0; jj < 4; jj++) acc[it][jj] = 0ULL;

#pragma unroll 4
    for (int k0 = 0; k0 < KD; k0 += 4) {
        float xin[NT][4];
#pragma unroll
        for (int it = 0; it < NT; it++) {
            float4 v = *(const float4*)(in_s + (tg*NT + it)*in_stride + k0);
            xin[it][0] = v.x; xin[it][1] = v.y; xin[it][2] = v.z; xin[it][3] = v.w;
        }
#pragma unroll
        for (int kk = 0; kk < 4; kk++) {
            unsigned long long wp[4];
#pragma unroll
            for (int jj = 0; jj < 4; jj++)
                wp[jj] = *(const unsigned long long*)(w_s + (k0+kk)*64 + jg*2 + 16*jj);
#pragma unroll
            for (int it = 0; it < NT; it++) {
                unsigned long long xd = dup2(xin[it][kk]);
#pragma unroll
                for (int jj = 0; jj < 4; jj++) ffma2(acc[it][jj], xd, wp[jj]);
            }
        }
    }
#pragma unroll
    for (int it = 0; it < NT; it++) {
        int t = tg*NT + it;
#pragma unroll
        for (int jj = 0; jj < 4; jj++) {
            int j0 = jg*2 + 16*jj;
            float v0 = lo32(acc[it][jj]) + bj[jj][0];
            float v1 = hi32(acc[it][jj]) + bj[jj][1];
            if (RELU) { v0 = fmaxf(v0, 0.0f); v1 = fmaxf(v1, 0.0f); }
            if (OUTMODE == 0) {
                out_s[t*64 + j0]     = v0;
                out_s[t*64 + j0 + 1] = v1;
            } else {
                out_s[j0*XT_STRIDE + t]       = v0;
                out_s[(j0 + 1)*XT_STRIDE + t] = v1;
            }
        }
    }
}

// ---------------- prep: fragment-order fp16 hi/lo pack + exact e2 ----------------
__global__ void prep_kernel(const float* __restrict__ cb) {
    int gt = blockIdx.x * 256 + threadIdx.x;
    int c  = gt >> 2;
    int q  = gt & 3;
    if (c >= CODEBOOK) return;

    uint32_t hw[8], lw[8];
    float sq = 0.0f;
#pragma unroll
    for (int s = 0; s < 8; s++) {
        int kb = s >> 1, b = s & 1;
        int w  = kb*8 + 4*b + q;
        float x0 = __ldg(cb + (size_t)c*OUT_DIM + 2*w);
        float x1 = __ldg(cb + (size_t)c*OUT_DIM + 2*w + 1);
        split_h2(x0, x1, hw[s], lw[s]);
        sq += x0*x0 + x1*x1;
    }
    uint32_t* pack = (uint32_t*)g_cbpack4;
    uint32_t* hrow = pack + c*CBW + q*8;
    uint32_t* lrow = hrow + CODEBOOK*CBW;
    *(uint4*)(hrow)     = make_uint4(hw[0], hw[1], hw[2], hw[3]);
    *(uint4*)(hrow + 4) = make_uint4(hw[4], hw[5], hw[6], hw[7]);
    *(uint4*)(lrow)     = make_uint4(lw[0], lw[1], lw[2], lw[3]);
    *(uint4*)(lrow + 4) = make_uint4(lw[4], lw[5], lw[6], lw[7]);

    sq += __shfl_xor_sync(0xffffffffu, sq, 1);
    sq += __shfl_xor_sync(0xffffffffu, sq, 2);
    if (q == 0) g_e2[c] = sq;
}

// ---------------- staging: pure uint4 copy ----------------
__device__ __forceinline__ void b_ldg(int ch, int tid, uint4* v) {
    const uint4* hb = g_cbpack4 + (size_t)ch*CCH*(CBW/4);
    const uint4* lb = hb + CODEBOOK*(CBW/4);
    v[0] = __ldg(hb + tid);
    v[1] = __ldg(hb + tid + 256);
    v[2] = __ldg(lb + tid);
    v[3] = __ldg(lb + tid + 256);
}
__device__ __forceinline__ void b_sts(uint32_t* bbuf, int tid, const uint4* v) {
#pragma unroll
    for (int i = 0; i < 2; i++) {
        int idx = tid + i*256;
        int c0 = idx >> 3, sub = idx & 7;
        *(uint4*)(bbuf + c0*B_ROW_W + sub*4)            = v[i];
        *(uint4*)(bbuf + B_TILE_W + c0*B_ROW_W + sub*4) = v[i+2];
    }
}

// ---------------- fused kernel ----------------
__global__ void __launch_bounds__(NTHREADS, 2)
vq_main(const float* __restrict__ obs,
        const float* __restrict__ W1, const float* __restrict__ b1,
        const float* __restrict__ W2, const float* __restrict__ b2,
        const float* __restrict__ W3, const float* __restrict__ b3,
        const float* __restrict__ cb,
        float* __restrict__ out)
{
    extern __shared__ float sm[];
    const int tid  = threadIdx.x;
    const int wid  = tid >> 5;
    const int lane = tid & 31;
    const int r    = lane >> 2;
    const int q    = lane & 3;
    const int tok0 = blockIdx.x * TB;

    for (int i = tid; i < CODEBOOK; i += NTHREADS) sm[OFF_E2 + i] = g_e2[i];

    // ================= MLP =================
    {
        const float4* w4 = (const float4*)W1;
        float4* d4 = (float4*)(sm + OFF_W);
        for (int i = tid; i < (IN_DIM*HID)/4; i += NTHREADS) d4[i] = w4[i];
    }
    for (int half = 0; half < 2; half++) {
        __syncthreads();
        const float4* o4 = (const float4*)(obs + (size_t)(tok0 + half*64) * IN_DIM);
        float4* d4 = (float4*)(sm + OFF_OBS);
        for (int i = tid; i < (64*IN_DIM)/4; i += NTHREADS) d4[i] = o4[i];
        __syncthreads();
        mlp_layer<IN_DIM, 2, 0, true>(sm + OFF_OBS, IN_DIM, sm + OFF_W, b1,
                                      sm + OFF_H1 + half*64*HID, tid);
    }
    __syncthreads();
    {
        const float4* w4 = (const float4*)W2;
        float4* d4 = (float4*)(sm + OFF_W);
        for (int i = tid; i < (HID*HID)/4; i += NTHREADS) d4[i] = w4[i];
    }
    __syncthreads();
    mlp_layer<HID, 4, 0, true>(sm + OFF_H1, HID, sm + OFF_W, b2, sm + OFF_OBS, tid);
    __syncthreads();
    {
        const float4* w4 = (const float4*)W3;
        float4* d4 = (float4*)(sm + OFF_W);
        for (int i = tid; i < (HID*OUT_DIM)/4; i += NTHREADS) d4[i] = w4[i];
    }
    __syncthreads();
    mlp_layer<HID, 4, 1, false>(sm + OFF_OBS, HID, sm + OFF_W, b3, sm + OFF_XT, tid);
    __syncthreads();

    // ========== A fragments: TWO m16 tiles per warp (32 tokens) ==========
    const float* xsT = sm + OFF_XT;
    const int wtile  = wid & 3;          // token group: 4 groups x 32 tokens
    const int whalf  = wid >> 2;         // code half within each chunk (0: 0..31, 1: 32..63)
    const int tokw32 = wtile * 32;

    uint32_t Ah[2][4][4], Al[2][4][4];
#pragma unroll
    for (int tl = 0; tl < 2; tl++) {
#pragma unroll
        for (int kb = 0; kb < 4; kb++) {
            int k0 = kb*16;
            const float* x0 = xsT + tokw32 + tl*16;
            float v00 = x0[(k0 + 2*q    )*XT_STRIDE + r];
            float v01 = x0[(k0 + 2*q + 1)*XT_STRIDE + r];
            float v10 = x0[(k0 + 2*q    )*XT_STRIDE + r + 8];
            float v11 = x0[(k0 + 2*q + 1)*XT_STRIDE + r + 8];
            float v20 = x0[(k0 + 2*q + 8)*XT_STRIDE + r];
            float v21 = x0[(k0 + 2*q + 9)*XT_STRIDE + r];
            float v30 = x0[(k0 + 2*q + 8)*XT_STRIDE + r + 8];
            float v31 = x0[(k0 + 2*q + 9)*XT_STRIDE + r + 8];
            split_h2(v00, v01, Ah[tl][kb][0], Al[tl][kb][0]);
            split_h2(v10, v11, Ah[tl][kb][1], Al[tl][kb][1]);
            split_h2(v20, v21, Ah[tl][kb][2], Al[tl][kb][2]);
            split_h2(v30, v31, Ah[tl][kb][3], Al[tl][kb][3]);
        }
    }

    // ================= VQ sweep: each warp = 2 m-tiles x half-chunk codes =================
    // best pairs: p=0..3 -> token tokw32 + r + 8*p
    float best_d[4];
    int   best_c[4];
#pragma unroll
    for (int p = 0; p < 4; p++) { best_d[p] = FLT_MAX; best_c[p] = 0; }

    uint32_t* bw = (uint32_t*)(sm + OFF_B);
    {
        uint4 st[4];
        b_ldg(0, tid, st);
        b_sts(bw, tid, st);
        __syncthreads();
    }

    for (int ch = 0; ch < NCH; ch++) {
        const int buf = ch % 3;
        uint4 pv[4];
        const bool more = (ch + 1 < NCH);
        if (more) b_ldg(ch + 1, tid, pv);

        const uint32_t* bb = bw + buf*B_BUF_W;

#pragma unroll
        for (int gp2 = 0; gp2 < 2; gp2++) {
            const uint32_t* pa = bb + (whalf*32 + gp2*16 + r)*B_ROW_W + q*8;
            const uint32_t* pb = pa + 8*B_ROW_W;

            float a0a[4]={0,0,0,0}, a0b[4]={0,0,0,0};   // tile0, code blocks a/b
            float a1a[4]={0,0,0,0}, a1b[4]={0,0,0,0};   // tile1

            {   // kb-pair 0/1
                uint4 ha = *(const uint4*)(pa);
                uint4 hb = *(const uint4*)(pb);
                uint4 la = *(const uint4*)(pa + B_TILE_W);
                uint4 lb = *(const uint4*)(pb + B_TILE_W);
                // kb0: hh, hl, lh (order identical to r13 per chain)
                mma16(a0a, Ah[0][0], ha.x, ha.y);  mma16(a0b, Ah[0][0], hb.x, hb.y);
                mma16(a1a, Ah[1][0], ha.x, ha.y);  mma16(a1b, Ah[1][0], hb.x, hb.y);
                mma16(a0a, Ah[0][0], la.x, la.y);  mma16(a0b, Ah[0][0], lb.x, lb.y);
                mma16(a1a, Ah[1][0], la.x, la.y);  mma16(a1b, Ah[1][0], lb.x, lb.y);
                mma16(a0a, Al[0][0], ha.x, ha.y);  mma16(a0b, Al[0][0], hb.x, hb.y);
                mma16(a1a, Al[1][0], ha.x, ha.y);  mma16(a1b, Al[1][0], hb.x, hb.y);
                // kb1
                mma16(a0a, Ah[0][1], ha.z, ha.w);  mma16(a0b, Ah[0][1], hb.z, hb.w);
                mma16(a1a, Ah[1][1], ha.z, ha.w);  mma16(a1b, Ah[1][1], hb.z, hb.w);
                mma16(a0a, Ah[0][1], la.z, la.w);  mma16(a0b, Ah[0][1], lb.z, lb.w);
                mma16(a1a, Ah[1][1], la.z, la.w);  mma16(a1b, Ah[1][1], lb.z, lb.w);
                mma16(a0a, Al[0][1], ha.z, ha.w);  mma16(a0b, Al[0][1], hb.z, hb.w);
                mma16(a1a, Al[1][1], ha.z, ha.w);  mma16(a1b, Al[1][1], hb.z, hb.w);
            }
            {   // kb-pair 2/3
                uint4 ha = *(const uint4*)(pa + 4);
                uint4 hb = *(const uint4*)(pb + 4);
                uint4 la = *(const uint4*)(pa + B_TILE_W + 4);
                uint4 lb = *(const uint4*)(pb + B_TILE_W + 4);
                // kb2
                mma16(a0a, Ah[0][2], ha.x, ha.y);  mma16(a0b, Ah[0][2], hb.x, hb.y);
                mma16(a1a, Ah[1][2], ha.x, ha.y);  mma16(a1b, Ah[1][2], hb.x, hb.y);
                mma16(a0a, Ah[0][2], la.x, la.y);  mma16(a0b, Ah[0][2], lb.x, lb.y);
                mma16(a1a, Ah[1][2], la.x, la.y);  mma16(a1b, Ah[1][2], lb.x, lb.y);
                mma16(a0a, Al[0][2], ha.x, ha.y);  mma16(a0b, Al[0][2], hb.x, hb.y);
                mma16(a1a, Al[1][2], ha.x, ha.y);  mma16(a1b, Al[1][2], hb.x, hb.y);
                // kb3
                mma16(a0a, Ah[0][3], ha.z, ha.w);  mma16(a0b, Ah[0][3], hb.z, hb.w);
                mma16(a1a, Ah[1][3], ha.z, ha.w);  mma16(a1b, Ah[1][3], hb.z, hb.w);
                mma16(a0a, Ah[0][3], la.z, la.w);  mma16(a0b, Ah[0][3], lb.z, lb.w);
                mma16(a1a, Ah[1][3], la.z, la.w);  mma16(a1b, Ah[1][3], lb.z, lb.w);
                mma16(a0a, Al[0][3], ha.z, ha.w);  mma16(a0b, Al[0][3], hb.z, hb.w);
                mma16(a1a, Al[1][3], ha.z, ha.w);  mma16(a1b, Al[1][3], hb.z, hb.w);
            }

            // epilogue: code blocks ascending (a: +0..7, b: +8..15)
            int codeA = ch*CCH + whalf*32 + gp2*16 + 2*q;
            int codeB = codeA + 8;
            float e2A0 = sm[OFF_E2 + codeA],     e2A1 = sm[OFF_E2 + codeA + 1];
            float e2B0 = sm[OFF_E2 + codeB],     e2B1 = sm[OFF_E2 + codeB + 1];

#pragma unroll
            for (int tl = 0; tl < 2; tl++) {
                const float* ca = tl ? a1a : a0a;
                const float* cbk = tl ? a1b : a0b;
                int p0 = tl*2, p1 = tl*2 + 1;   // pairs: row r -> p0, row r+8 -> p1
                // block a
                float d0 = fmaf(-2.0f, ca[0], e2A0);
                float d1 = fmaf(-2.0f, ca[1], e2A1);
                float d2 = fmaf(-2.0f, ca[2], e2A0);
                float d3 = fmaf(-2.0f, ca[3], e2A1);
                if (d0 < best_d[p0]) { best_d[p0] = d0; best_c[p0] = codeA; }
                if (d1 < best_d[p0]) { best_d[p0] = d1; best_c[p0] = codeA + 1; }
                if (d2 < best_d[p1]) { best_d[p1] = d2; best_c[p1] = codeA; }
                if (d3 < best_d[p1]) { best_d[p1] = d3; best_c[p1] = codeA + 1; }
                // block b
                float e0 = fmaf(-2.0f, cbk[0], e2B0);
                float e1 = fmaf(-2.0f, cbk[1], e2B1);
                float e2v = fmaf(-2.0f, cbk[2], e2B0);
                float e3 = fmaf(-2.0f, cbk[3], e2B1);
                if (e0 < best_d[p0]) { best_d[p0] = e0; best_c[p0] = codeB; }
                if (e1 < best_d[p0]) { best_d[p0] = e1; best_c[p0] = codeB + 1; }
                if (e2v < best_d[p1]) { best_d[p1] = e2v; best_c[p1] = codeB; }
                if (e3 < best_d[p1]) { best_d[p1] = e3; best_c[p1] = codeB + 1; }
            }
        }

        if (more) b_sts(bw + ((ch + 1) % 3)*B_BUF_W, tid, pv);
        __syncthreads();
    }

    // ---- cross-lane argmin (4 q-lanes), tie-break smaller code ----
#pragma unroll
    for (int m = 1; m <= 2; m <<= 1) {
#pragma unroll
        for (int p = 0; p < 4; p++) {
            float od = __shfl_xor_sync(0xffffffffu, best_d[p], m);
            int   oc = __shfl_xor_sync(0xffffffffu, best_c[p], m);
            if (od < best_d[p] || (od == best_d[p] && oc < best_c[p])) {
                best_d[p] = od; best_c[p] = oc;
            }
        }
    }

    // ---- cross-warp-half combine (each token has 2 candidates: code halves) ----
    float2* sRed = (float2*)(sm + OFF_B);     // [128 tokens][2 halves]
    if (q == 0) {
#pragma unroll
        for (int p = 0; p < 4; p++) {
            int t = tokw32 + r + 8*p;
            sRed[t*2 + whalf] = make_float2(best_d[p], __int_as_float(best_c[p]));
        }
    }
    __syncthreads();

    int* sIdx = (int*)(sm + OFF_B + 512);
    if (tid < TB) {
        float2 a = sRed[tid*2 + 0];
        float2 b = sRed[tid*2 + 1];
        int ca = __float_as_int(a.y), cbi = __float_as_int(b.y);
        int bc = (a.x < b.x || (a.x == b.x && ca < cbi)) ? ca : cbi;
        sIdx[tid] = bc;
        out[IDX_OFF + (size_t)(tok0 + tid)] = (float)bc;
    }
    __syncthreads();

    // ---- msg write + commitment-loss partial ----
    float part = 0.0f;
    for (int f = tid; f < TB*OUT_DIM; f += NTHREADS) {
        int t = f >> 6, j = f & 63;
        int c = sIdx[t];
        float qv = __ldg(cb + (size_t)c * OUT_DIM + j);
        float xv = xsT[j*XT_STRIDE + t];
        out[(size_t)(tok0 + t)*OUT_DIM + j] = xv + (qv - xv);
        float dd = qv - xv;
        part += dd * dd;
    }
#pragma unroll
    for (int o = 16; o > 0; o >>= 1)
        part += __shfl_down_sync(0xffffffffu, part, o);
    __shared__ float swred[8];
    __shared__ int isLast;
    if ((tid & 31) == 0) swred[tid >> 5] = part;
    __syncthreads();
    if (tid == 0) {
        float s = 0.0f;
#pragma unroll
        for (int w = 0; w < 8; w++) s += swred[w];
        g_partial[blockIdx.x] = s;
        __threadfence();
        isLast = (atomicAdd(&g_done, 1) == NBLOCKS - 1);
    }
    __syncthreads();

    // ---- last block: deterministic loss reduction ----
    if (isLast) {
        volatile float* gp = g_partial;
        float* red = sm + 512;               // E2 region, dead
        red[tid] = gp[tid] + gp[tid + NTHREADS];
        __syncthreads();
        for (int o = NTHREADS/2; o > 0; o >>= 1) {
            if (tid < o) red[tid] += red[tid + o];
            __syncthreads();
        }
        if (tid == 0) {
            out[LOSS_OFF] = red[0] * (1.0f / (float)MSG_ELEMS);
            g_done = 0;
        }
    }
}

extern "C" void kernel_launch(void* const* d_in, const int* in_sizes, int n_in,
                              void* d_out, int out_size)
{
    const float* obs = (const float*)d_in[0];
    const float* W1  = (const float*)d_in[1];
    const float* b1  = (const float*)d_in[2];
    const float* W2  = (const float*)d_in[3];
    const float* b2  = (const float*)d_in[4];
    const float* W3  = (const float*)d_in[5];
    const float* b3  = (const float*)d_in[6];
    const float* cb  = (const float*)d_in[7];
    float* out = (float*)d_out;

    cudaFuncSetAttribute(vq_main, cudaFuncAttributeMaxDynamicSharedMemorySize,
                         SMEM_FLOATS * (int)sizeof(float));

    prep_kernel<<<(CODEBOOK*4 + 255)/256, 256>>>(cb);
    vq_main<<<NBLOCKS, NTHREADS, SMEM_FLOATS * sizeof(float)>>>(
        obs, W1, b1, W2, b2, W3, b3, cb, out);
}

// round 15
// speedup vs baseline: 1.4631x; 1.2105x over previous
#include <cuda_runtime.h>
#include <cuda_fp16.h>
#include <math.h>
#include <float.h>
#include <stdint.h>

// ---------------- problem constants ----------------
#define TOKENS_TOTAL (32*2048)
#define IN_DIM   128
#define HID      64
#define OUT_DIM  64
#define CODEBOOK 2048

#define TB       128
#define NTHREADS 256
#define NBLOCKS  (TOKENS_TOTAL/TB)     // 512
#define XT_STRIDE 130
#define CCH      64
#define NCH      (CODEBOOK/CCH)        // 32

// output layout: msg ++ idx(as float) ++ loss
#define MSG_ELEMS ((size_t)TOKENS_TOTAL*OUT_DIM)
#define IDX_OFF   MSG_ELEMS
#define LOSS_OFF  (MSG_ELEMS + TOKENS_TOTAL)

// ---------------- smem layout (word offsets) ----------------
#define OFF_E2   0                      // 2048 f (also reused for loss tree at +512)
#define OFF_XT   2048                   // 64 x 130 f -> end 10368
#define OFF_B    10368                  // 3 bufs x (hi 64x36 + lo 64x36) = 13824 w -> 24192
#define B_ROW_W   36
#define B_TILE_W  (CCH*B_ROW_W)         // 2304
#define B_BUF_W   (2*B_TILE_W)          // 4608
#define SMEM_FLOATS 24192               // 96768 B ; x2 CTAs fits easily

// packed codebook, FRAGMENT ORDER (r5/r10-verified)
#define CBW 32
__device__ uint4 g_cbpack4[2 * CODEBOOK * CBW / 4];
// packed MLP weights, fragment order: W1 [0,2048), W2 [2048,3072), W3 [3072,4096)
// entry (kb*NB+nb)*32 + lane = {b0h, b1h, b0l, b1l}
__device__ uint4 g_wpack4[4096];
__device__ float g_e2[CODEBOOK];
__device__ float g_partial[NBLOCKS];
__device__ int   g_done = 0;

// ---------------- fp16 split helpers ----------------
__device__ __forceinline__ void split_h2(float x0, float x1, uint32_t& h, uint32_t& l) {
    __half h0 = __float2half_rn(x0);
    __half h1 = __float2half_rn(x1);
    float  l0 = x0 - __half2float(h0);
    float  l1 = x1 - __half2float(h1);
    __half2 hh = __halves2half2(h0, h1);
    __half2 ll = __floats2half2_rn(l0, l1);
    h = *(uint32_t*)&hh;
    l = *(uint32_t*)&ll;
}

__device__ __forceinline__ void mma16(float* c, const uint32_t* a, uint32_t b0, uint32_t b1) {
    asm volatile(
        "mma.sync.aligned.m16n8k16.row.col.f32.f16.f16.f32 "
        "{%0,%1,%2,%3}, {%4,%5,%6,%7}, {%8,%9}, {%0,%1,%2,%3};"
        : "+f"(c[0]), "+f"(c[1]), "+f"(c[2]), "+f"(c[3])
        : "r"(a[0]), "r"(a[1]), "r"(a[2]), "r"(a[3]), "r"(b0), "r"(b1));
}

// ---------------- prep: codebook pack + e2 + weight pack ----------------
__global__ void prep_kernel(const float* __restrict__ cb,
                            const float* __restrict__ W1,
                            const float* __restrict__ W2,
                            const float* __restrict__ W3) {
    int gt = blockIdx.x * 256 + threadIdx.x;
    if (gt < CODEBOOK*4) {
        int c  = gt >> 2;
        int q  = gt & 3;
        uint32_t hw[8], lw[8];
        float sq = 0.0f;
#pragma unroll
        for (int s = 0; s < 8; s++) {
            int kb = s >> 1, b = s & 1;
            int w  = kb*8 + 4*b + q;
            float x0 = __ldg(cb + (size_t)c*OUT_DIM + 2*w);
            float x1 = __ldg(cb + (size_t)c*OUT_DIM + 2*w + 1);
            split_h2(x0, x1, hw[s], lw[s]);
            sq += x0*x0 + x1*x1;
        }
        uint32_t* pack = (uint32_t*)g_cbpack4;
        uint32_t* hrow = pack + c*CBW + q*8;
        uint32_t* lrow = hrow + CODEBOOK*CBW;
        *(uint4*)(hrow)     = make_uint4(hw[0], hw[1], hw[2], hw[3]);
        *(uint4*)(hrow + 4) = make_uint4(hw[4], hw[5], hw[6], hw[7]);
        *(uint4*)(lrow)     = make_uint4(lw[0], lw[1], lw[2], lw[3]);
        *(uint4*)(lrow + 4) = make_uint4(lw[4], lw[5], lw[6], lw[7]);

        sq += __shfl_xor_sync(0xffffffffu, sq, 1);
        sq += __shfl_xor_sync(0xffffffffu, sq, 2);
        if (q == 0) g_e2[c] = sq;
    } else if (gt < CODEBOOK*4 + 4096) {
        int widx = gt - CODEBOOK*4;      // 0..4095
        const float* W; int off; int local;
        if (widx < 2048)      { W = W1; off = 0;    local = widx; }
        else if (widx < 3072) { W = W2; off = 2048; local = widx - 2048; }
        else                  { W = W3; off = 3072; local = widx - 3072; }
        int lane = local & 31;
        int nb   = (local >> 5) & 7;
        int kb   = local >> 8;
        int qq = lane & 3, rr = lane >> 2;
        int n  = nb*8 + rr;
        int k0 = kb*16 + 2*qq;
        float w00 = __ldg(W + (size_t)(k0    )*64 + n);
        float w01 = __ldg(W + (size_t)(k0 + 1)*64 + n);
        float w10 = __ldg(W + (size_t)(k0 + 8)*64 + n);
        float w11 = __ldg(W + (size_t)(k0 + 9)*64 + n);
        uint32_t b0h, b0l, b1h, b1l;
        split_h2(w00, w01, b0h, b0l);
        split_h2(w10, w11, b1h, b1l);
        g_wpack4[off + local] = make_uint4(b0h, b1h, b0l, b1l);
    }
}

// ---------------- staging: pure uint4 copy ----------------
__device__ __forceinline__ void b_ldg(int ch, int tid, uint4* v) {
    const uint4* hb = g_cbpack4 + (size_t)ch*CCH*(CBW/4);
    const uint4* lb = hb + CODEBOOK*(CBW/4);
    v[0] = __ldg(hb + tid);
    v[1] = __ldg(hb + tid + 256);
    v[2] = __ldg(lb + tid);
    v[3] = __ldg(lb + tid + 256);
}
__device__ __forceinline__ void b_sts(uint32_t* bbuf, int tid, const uint4* v) {
#pragma unroll
    for (int i = 0; i < 2; i++) {
        int idx = tid + i*256;
        int c0 = idx >> 3, sub = idx & 7;
        *(uint4*)(bbuf + c0*B_ROW_W + sub*4)            = v[i];
        *(uint4*)(bbuf + B_TILE_W + c0*B_ROW_W + sub*4) = v[i+2];
    }
}

// ---------------- fused kernel ----------------
__global__ void __launch_bounds__(NTHREADS, 2)
vq_main(const float* __restrict__ obs,
        const float* __restrict__ W1, const float* __restrict__ b1,
        const float* __restrict__ W2, const float* __restrict__ b2,
        const float* __restrict__ W3, const float* __restrict__ b3,
        const float* __restrict__ cb,
        float* __restrict__ out)
{
    extern __shared__ float sm[];
    const int tid  = threadIdx.x;
    const int wid  = tid >> 5;
    const int lane = tid & 31;
    const int r    = lane >> 2;
    const int q    = lane & 3;
    const int tok0 = blockIdx.x * TB;
    const int tokw = wid * 16;

    for (int i = tid; i < CODEBOOK; i += NTHREADS) sm[OFF_E2 + i] = g_e2[i];

    // ================= MLP on tensor cores: per-warp m16 tile, register-resident =================
    {
        float acc[8][4];
#pragma unroll
        for (int nb = 0; nb < 8; nb++)
#pragma unroll
            for (int j = 0; j < 4; j++) acc[nb][j] = 0.f;

        const float* r0 = obs + (size_t)(tok0 + tokw + r)*IN_DIM;
        const float* r8 = r0 + 8*IN_DIM;

        // ---- layer 1: obs[16 x 128] @ W1[128 x 64] ----
#pragma unroll
        for (int kb = 0; kb < 8; kb++) {
            int k0 = kb*16 + 2*q;
            float2 p0 = *(const float2*)(r0 + k0);
            float2 p1 = *(const float2*)(r8 + k0);
            float2 p2 = *(const float2*)(r0 + k0 + 8);
            float2 p3 = *(const float2*)(r8 + k0 + 8);
            uint32_t ah[4], al[4];
            split_h2(p0.x, p0.y, ah[0], al[0]);
            split_h2(p1.x, p1.y, ah[1], al[1]);
            split_h2(p2.x, p2.y, ah[2], al[2]);
            split_h2(p3.x, p3.y, ah[3], al[3]);
#pragma unroll
            for (int nb = 0; nb < 8; nb++) {
                uint4 wv = __ldg(g_wpack4 + (kb*8 + nb)*32 + lane);
                mma16(acc[nb], ah, wv.x, wv.y);
                mma16(acc[nb], ah, wv.z, wv.w);
                mma16(acc[nb], al, wv.x, wv.y);
            }
        }

        // ---- bias + relu + re-split: C fragments -> next-layer A fragments ----
        uint32_t Fh[4][4], Fl[4][4];
#pragma unroll
        for (int kb2 = 0; kb2 < 4; kb2++) {
#pragma unroll
            for (int hf = 0; hf < 2; hf++) {
                int nb = kb2*2 + hf;
                float bb0 = __ldg(b1 + nb*8 + 2*q);
                float bb1 = __ldg(b1 + nb*8 + 2*q + 1);
                float h0 = fmaxf(acc[nb][0] + bb0, 0.f);
                float h1 = fmaxf(acc[nb][1] + bb1, 0.f);
                float h2 = fmaxf(acc[nb][2] + bb0, 0.f);
                float h3 = fmaxf(acc[nb][3] + bb1, 0.f);
                split_h2(h0, h1, Fh[kb2][hf*2],     Fl[kb2][hf*2]);
                split_h2(h2, h3, Fh[kb2][hf*2 + 1], Fl[kb2][hf*2 + 1]);
            }
        }

        // ---- layer 2: h1[16 x 64] @ W2[64 x 64] ----
        float acc2[8][4];
#pragma unroll
        for (int nb = 0; nb < 8; nb++)
#pragma unroll
            for (int j = 0; j < 4; j++) acc2[nb][j] = 0.f;
#pragma unroll
        for (int kb = 0; kb < 4; kb++)
#pragma unroll
            for (int nb = 0; nb < 8; nb++) {
                uint4 wv = __ldg(g_wpack4 + 2048 + (kb*8 + nb)*32 + lane);
                mma16(acc2[nb], Fh[kb], wv.x, wv.y);
                mma16(acc2[nb], Fh[kb], wv.z, wv.w);
                mma16(acc2[nb], Fl[kb], wv.x, wv.y);
            }

        // ---- bias + relu + re-split ----
#pragma unroll
        for (int kb2 = 0; kb2 < 4; kb2++) {
#pragma unroll
            for (int hf = 0; hf < 2; hf++) {
                int nb = kb2*2 + hf;
                float bb0 = __ldg(b2 + nb*8 + 2*q);
                float bb1 = __ldg(b2 + nb*8 + 2*q + 1);
                float h0 = fmaxf(acc2[nb][0] + bb0, 0.f);
                float h1 = fmaxf(acc2[nb][1] + bb1, 0.f);
                float h2 = fmaxf(acc2[nb][2] + bb0, 0.f);
                float h3 = fmaxf(acc2[nb][3] + bb1, 0.f);
                split_h2(h0, h1, Fh[kb2][hf*2],     Fl[kb2][hf*2]);
                split_h2(h2, h3, Fh[kb2][hf*2 + 1], Fl[kb2][hf*2 + 1]);
            }
        }

        // ---- layer 3: h2[16 x 64] @ W3[64 x 64] (no relu) ----
#pragma unroll
        for (int nb = 0; nb < 8; nb++)
#pragma unroll
            for (int j = 0; j < 4; j++) acc[nb][j] = 0.f;
#pragma unroll
        for (int kb = 0; kb < 4; kb++)
#pragma unroll
            for (int nb = 0; nb < 8; nb++) {
                uint4 wv = __ldg(g_wpack4 + 3072 + (kb*8 + nb)*32 + lane);
                mma16(acc[nb], Fh[kb], wv.x, wv.y);
                mma16(acc[nb], Fh[kb], wv.z, wv.w);
                mma16(acc[nb], Fl[kb], wv.x, wv.y);
            }

        // ---- x = C + b3 -> XT smem (transposed) ----
        float* base = sm + OFF_XT;
#pragma unroll
        for (int nb = 0; nb < 8; nb++) {
            int n0 = nb*8 + 2*q;
            float bb0 = __ldg(b3 + n0);
            float bb1 = __ldg(b3 + n0 + 1);
            base[(n0    )*XT_STRIDE + tokw + r]     = acc[nb][0] + bb0;
            base[(n0 + 1)*XT_STRIDE + tokw + r]     = acc[nb][1] + bb1;
            base[(n0    )*XT_STRIDE + tokw + r + 8] = acc[nb][2] + bb0;
            base[(n0 + 1)*XT_STRIDE + tokw + r + 8] = acc[nb][3] + bb1;
        }
    }
    __syncthreads();

    // ========== A fragments: TWO m16 tiles per warp (32 tokens) — r14 verbatim ==========
    const float* xsT = sm + OFF_XT;
    const int wtile  = wid & 3;
    const int whalf  = wid >> 2;
    const int tokw32 = wtile * 32;

    uint32_t Ah[2][4][4], Al[2][4][4];
#pragma unroll
    for (int tl = 0; tl < 2; tl++) {
#pragma unroll
        for (int kb = 0; kb < 4; kb++) {
            int k0 = kb*16;
            const float* x0 = xsT + tokw32 + tl*16;
            float v00 = x0[(k0 + 2*q    )*XT_STRIDE + r];
            float v01 = x0[(k0 + 2*q + 1)*XT_STRIDE + r];
            float v10 = x0[(k0 + 2*q    )*XT_STRIDE + r + 8];
            float v11 = x0[(k0 + 2*q + 1)*XT_STRIDE + r + 8];
            float v20 = x0[(k0 + 2*q + 8)*XT_STRIDE + r];
            float v21 = x0[(k0 + 2*q + 9)*XT_STRIDE + r];
            float v30 = x0[(k0 + 2*q + 8)*XT_STRIDE + r + 8];
            float v31 = x0[(k0 + 2*q + 9)*XT_STRIDE + r + 8];
            split_h2(v00, v01, Ah[tl][kb][0], Al[tl][kb][0]);
            split_h2(v10, v11, Ah[tl][kb][1], Al[tl][kb][1]);
            split_h2(v20, v21, Ah[tl][kb][2], Al[tl][kb][2]);
            split_h2(v30, v31, Ah[tl][kb][3], Al[tl][kb][3]);
        }
    }

    // ================= VQ sweep (r14 verbatim) =================
    float best_d[4];
    int   best_c[4];
#pragma unroll
    for (int p = 0; p < 4; p++) { best_d[p] = FLT_MAX; best_c[p] = 0; }

    uint32_t* bw = (uint32_t*)(sm + OFF_B);
    {
        uint4 st[4];
        b_ldg(0, tid, st);
        b_sts(bw, tid, st);
        __syncthreads();
    }

    for (int ch = 0; ch < NCH; ch++) {
        const int buf = ch % 3;
        uint4 pv[4];
        const bool more = (ch + 1 < NCH);
        if (more) b_ldg(ch + 1, tid, pv);

        const uint32_t* bb = bw + buf*B_BUF_W;

#pragma unroll
        for (int gp2 = 0; gp2 < 2; gp2++) {
            const uint32_t* pa = bb + (whalf*32 + gp2*16 + r)*B_ROW_W + q*8;
            const uint32_t* pb = pa + 8*B_ROW_W;

            float a0a[4]={0,0,0,0}, a0b[4]={0,0,0,0};
            float a1a[4]={0,0,0,0}, a1b[4]={0,0,0,0};

            {
                uint4 ha = *(const uint4*)(pa);
                uint4 hb = *(const uint4*)(pb);
                uint4 la = *(const uint4*)(pa + B_TILE_W);
                uint4 lb = *(const uint4*)(pb + B_TILE_W);
                mma16(a0a, Ah[0][0], ha.x, ha.y);  mma16(a0b, Ah[0][0], hb.x, hb.y);
                mma16(a1a, Ah[1][0], ha.x, ha.y);  mma16(a1b, Ah[1][0], hb.x, hb.y);
                mma16(a0a, Ah[0][0], la.x, la.y);  mma16(a0b, Ah[0][0], lb.x, lb.y);
                mma16(a1a, Ah[1][0], la.x, la.y);  mma16(a1b, Ah[1][0], lb.x, lb.y);
                mma16(a0a, Al[0][0], ha.x, ha.y);  mma16(a0b, Al[0][0], hb.x, hb.y);
                mma16(a1a, Al[1][0], ha.x, ha.y);  mma16(a1b, Al[1][0], hb.x, hb.y);
                mma16(a0a, Ah[0][1], ha.z, ha.w);  mma16(a0b, Ah[0][1], hb.z, hb.w);
                mma16(a1a, Ah[1][1], ha.z, ha.w);  mma16(a1b, Ah[1][1], hb.z, hb.w);
                mma16(a0a, Ah[0][1], la.z, la.w);  mma16(a0b, Ah[0][1], lb.z, lb.w);
                mma16(a1a, Ah[1][1], la.z, la.w);  mma16(a1b, Ah[1][1], lb.z, lb.w);
                mma16(a0a, Al[0][1], ha.z, ha.w);  mma16(a0b, Al[0][1], hb.z, hb.w);
                mma16(a1a, Al[1][1], ha.z, ha.w);  mma16(a1b, Al[1][1], hb.z, hb.w);
            }
            {
                uint4 ha = *(const uint4*)(pa + 4);
                uint4 hb = *(const uint4*)(pb + 4);
                uint4 la = *(const uint4*)(pa + B_TILE_W + 4);
                uint4 lb = *(const uint4*)(pb + B_TILE_W + 4);
                mma16(a0a, Ah[0][2], ha.x, ha.y);  mma16(a0b, Ah[0][2], hb.x, hb.y);
                mma16(a1a, Ah[1][2], ha.x, ha.y);  mma16(a1b, Ah[1][2], hb.x, hb.y);
                mma16(a0a, Ah[0][2], la.x, la.y);  mma16(a0b, Ah[0][2], lb.x, lb.y);
                mma16(a1a, Ah[1][2], la.x, la.y);  mma16(a1b, Ah[1][2], lb.x, lb.y);
                mma16(a0a, Al[0][2], ha.x, ha.y);  mma16(a0b, Al[0][2], hb.x, hb.y);
                mma16(a1a, Al[1][2], ha.x, ha.y);  mma16(a1b, Al[1][2], hb.x, hb.y);
                mma16(a0a, Ah[0][3], ha.z, ha.w);  mma16(a0b, Ah[0][3], hb.z, hb.w);
                mma16(a1a, Ah[1][3], ha.z, ha.w);  mma16(a1b, Ah[1][3], hb.z, hb.w);
                mma16(a0a, Ah[0][3], la.z, la.w);  mma16(a0b, Ah[0][3], lb.z, lb.w);
                mma16(a1a, Ah[1][3], la.z, la.w);  mma16(a1b, Ah[1][3], lb.z, lb.w);
                mma16(a0a, Al[0][3], ha.z, ha.w);  mma16(a0b, Al[0][3], hb.z, hb.w);
                mma16(a1a, Al[1][3], ha.z, ha.w);  mma16(a1b, Al[1][3], hb.z, hb.w);
            }

            int codeA = ch*CCH + whalf*32 + gp2*16 + 2*q;
            int codeB = codeA + 8;
            float e2A0 = sm[OFF_E2 + codeA], e2A1 = sm[OFF_E2 + codeA + 1];
            float e2B0 = sm[OFF_E2 + codeB], e2B1 = sm[OFF_E2 + codeB + 1];

#pragma unroll
            for (int tl = 0; tl < 2; tl++) {
                const float* ca  = tl ? a1a : a0a;
                const float* cbk = tl ? a1b : a0b;
                int p0 = tl*2, p1 = tl*2 + 1;
                float d0 = fmaf(-2.0f, ca[0], e2A0);
                float d1 = fmaf(-2.0f, ca[1], e2A1);
                float d2 = fmaf(-2.0f, ca[2], e2A0);
                float d3 = fmaf(-2.0f, ca[3], e2A1);
                if (d0 < best_d[p0]) { best_d[p0] = d0; best_c[p0] = codeA; }
                if (d1 < best_d[p0]) { best_d[p0] = d1; best_c[p0] = codeA + 1; }
                if (d2 < best_d[p1]) { best_d[p1] = d2; best_c[p1] = codeA; }
                if (d3 < best_d[p1]) { best_d[p1] = d3; best_c[p1] = codeA + 1; }
                float e0  = fmaf(-2.0f, cbk[0], e2B0);
                float e1  = fmaf(-2.0f, cbk[1], e2B1);
                float e2v = fmaf(-2.0f, cbk[2], e2B0);
                float e3  = fmaf(-2.0f, cbk[3], e2B1);
                if (e0  < best_d[p0]) { best_d[p0] = e0;  best_c[p0] = codeB; }
                if (e1  < best_d[p0]) { best_d[p0] = e1;  best_c[p0] = codeB + 1; }
                if (e2v < best_d[p1]) { best_d[p1] = e2v; best_c[p1] = codeB; }
                if (e3  < best_d[p1]) { best_d[p1] = e3;  best_c[p1] = codeB + 1; }
            }
        }

        if (more) b_sts(bw + ((ch + 1) % 3)*B_BUF_W, tid, pv);
        __syncthreads();
    }

    // ---- cross-lane argmin (4 q-lanes), tie-break smaller code ----
#pragma unroll
    for (int m = 1; m <= 2; m <<= 1) {
#pragma unroll
        for (int p = 0; p < 4; p++) {
            float od = __shfl_xor_sync(0xffffffffu, best_d[p], m);
            int   oc = __shfl_xor_sync(0xffffffffu, best_c[p], m);
            if (od < best_d[p] || (od == best_d[p] && oc < best_c[p])) {
                best_d[p] = od; best_c[p] = oc;
            }
        }
    }

    // ---- cross-warp-half combine ----
    float2* sRed = (float2*)(sm + OFF_B);
    if (q == 0) {
#pragma unroll
        for (int p = 0; p < 4; p++) {
            int t = tokw32 + r + 8*p;
            sRed[t*2 + whalf] = make_float2(best_d[p], __int_as_float(best_c[p]));
        }
    }
    __syncthreads();

    int* sIdx = (int*)(sm + OFF_B + 512);
    if (tid < TB) {
        float2 a = sRed[tid*2 + 0];
        float2 b = sRed[tid*2 + 1];
        int ca = __float_as_int(a.y), cbi = __float_as_int(b.y);
        int bc = (a.x < b.x || (a.x == b.x && ca < cbi)) ? ca : cbi;
        sIdx[tid] = bc;
        out[IDX_OFF + (size_t)(tok0 + tid)] = (float)bc;
    }
    __syncthreads();

    // ---- msg write + commitment-loss partial ----
    float part = 0.0f;
    for (int f = tid; f < TB*OUT_DIM; f += NTHREADS) {
        int t = f >> 6, j = f & 63;
        int c = sIdx[t];
        float qv = __ldg(cb + (size_t)c * OUT_DIM + j);
        float xv = xsT[j*XT_STRIDE + t];
        out[(size_t)(tok0 + t)*OUT_DIM + j] = xv + (qv - xv);
        float dd = qv - xv;
        part += dd * dd;
    }
#pragma unroll
    for (int o = 16; o > 0; o >>= 1)
        part += __shfl_down_sync(0xffffffffu, part, o);
    __shared__ float swred[8];
    __shared__ int isLast;
    if ((tid & 31) == 0) swred[tid >> 5] = part;
    __syncthreads();
    if (tid == 0) {
        float s = 0.0f;
#pragma unroll
        for (int w = 0; w < 8; w++) s += swred[w];
        g_partial[blockIdx.x] = s;
        __threadfence();
        isLast = (atomicAdd(&g_done, 1) == NBLOCKS - 1);
    }
    __syncthreads();

    // ---- last block: deterministic loss reduction ----
    if (isLast) {
        volatile float* gp = g_partial;
        float* red = sm + 512;
        red[tid] = gp[tid] + gp[tid + NTHREADS];
        __syncthreads();
        for (int o = NTHREADS/2; o > 0; o >>= 1) {
            if (tid < o) red[tid] += red[tid + o];
            __syncthreads();
        }
        if (tid == 0) {
            out[LOSS_OFF] = red[0] * (1.0f / (float)MSG_ELEMS);
            g_done = 0;
        }
    }
}

extern "C" void kernel_launch(void* const* d_in, const int* in_sizes, int n_in,
                              void* d_out, int out_size)
{
    const float* obs = (const float*)d_in[0];
    const float* W1  = (const float*)d_in[1];
    const float* b1  = (const float*)d_in[2];
    const float* W2  = (const float*)d_in[3];
    const float* b2  = (const float*)d_in[4];
    const float* W3  = (const float*)d_in[5];
    const float* b3  = (const float*)d_in[6];
    const float* cb  = (const float*)d_in[7];
    float* out = (float*)d_out;

    cudaFuncSetAttribute(vq_main, cudaFuncAttributeMaxDynamicSharedMemorySize,
                         SMEM_FLOATS * (int)sizeof(float));

    prep_kernel<<<(CODEBOOK*4 + 4096 + 255)/256, 256>>>(cb, W1, W2, W3);
    vq_main<<<NBLOCKS, NTHREADS, SMEM_FLOATS * sizeof(float)>>>(
        obs, W1, b1, W2, b2, W3, b3, cb, out);
}

// round 16
// speedup vs baseline: 1.6001x; 1.0936x over previous
#include <cuda_runtime.h>
#include <cuda_fp16.h>
#include <math.h>
#include <float.h>
#include <stdint.h>

// ---------------- problem constants ----------------
#define TOKENS_TOTAL (32*2048)
#define IN_DIM   128
#define HID      64
#define OUT_DIM  64
#define CODEBOOK 2048

#define TB       128
#define NTHREADS 256
#define NBLOCKS  (TOKENS_TOTAL/TB)     // 512
#define XT_STRIDE 130
#define CCH      64
#define NCH      (CODEBOOK/CCH)        // 32

#define MSG_ELEMS ((size_t)TOKENS_TOTAL*OUT_DIM)
#define IDX_OFF   MSG_ELEMS
#define LOSS_OFF  (MSG_ELEMS + TOKENS_TOTAL)

// ---------------- smem layout (word offsets) ----------------
#define OFF_E2   0                      // 2048 f (loss tree reuses +512)
#define OFF_XT   2048                   // 64 x 130 -> 10368
#define OFF_B    10368                  // 3 bufs x (hi 64x36) = 6912 -> 17280
#define B_ROW_W   36
#define B_TILE_W  (CCH*B_ROW_W)         // 2304
#define OFF_TAU  17280                  // 128 f -> 17408
#define OFF_RED  17408                  // 128 x 2 f -> 17664
#define OFF_Q    17664                  // 8 warps x 1024 u32 -> 25856
#define QCAP     1024
#define OFF_TBL  25856                  // 128 u64 = 256 w -> 26112
#define SMEM_FLOATS 26112               // 104448 B ; x2 CTAs = 209KB <= 228KB

// certified 1-term threshold coefficient: 2*Md = 2*2^-9 |x||e|; 2.5/512 adds 25% headroom
#define TAU_C (2.5f/512.0f)

// packed codebook hi tiles, FRAGMENT ORDER (r5/r10-verified): [2048 codes][32 words]
#define CBW 32
__device__ uint4 g_cbpack4[CODEBOOK * CBW / 4];     // 256 KB (hi only)
// packed MLP weights (r15-verified): W1 [0,2048), W2 [2048,3072), W3 [3072,4096)
__device__ uint4 g_wpack4[4096];
__device__ float g_e2[CODEBOOK];
__device__ int   g_e2max_bits;                      // static-zero; atomicMax idempotent per replay
__device__ float g_partial[NBLOCKS];
__device__ int   g_done = 0;

// ---------------- helpers ----------------
__device__ __forceinline__ void split_h2(float x0, float x1, uint32_t& h, uint32_t& l) {
    __half h0 = __float2half_rn(x0);
    __half h1 = __float2half_rn(x1);
    float  l0 = x0 - __half2float(h0);
    float  l1 = x1 - __half2float(h1);
    __half2 hh = __halves2half2(h0, h1);
    __half2 ll = __floats2half2_rn(l0, l1);
    h = *(uint32_t*)&hh;
    l = *(uint32_t*)&ll;
}
__device__ __forceinline__ void mma16(float* c, const uint32_t* a, uint32_t b0, uint32_t b1) {
    asm volatile(
        "mma.sync.aligned.m16n8k16.row.col.f32.f16.f16.f32 "
        "{%0,%1,%2,%3}, {%4,%5,%6,%7}, {%8,%9}, {%0,%1,%2,%3};"
        : "+f"(c[0]), "+f"(c[1]), "+f"(c[2]), "+f"(c[3])
        : "r"(a[0]), "r"(a[1]), "r"(a[2]), "r"(a[3]), "r"(b0), "r"(b1));
}
__device__ __forceinline__ uint32_t fkey(float d) {
    uint32_t u = __float_as_uint(d);
    return (u & 0x80000000u) ? ~u : (u | 0x80000000u);
}

// ---------------- prep: codebook hi pack + e2 + e2max + weight pack ----------------
__global__ void prep_kernel(const float* __restrict__ cb,
                            const float* __restrict__ W1,
                            const float* __restrict__ W2,
                            const float* __restrict__ W3) {
    int gt = blockIdx.x * 256 + threadIdx.x;
    if (gt < CODEBOOK*4) {
        int c = gt >> 2, q = gt & 3;
        uint32_t hw[8], lw;
        float sq = 0.0f;
#pragma unroll
        for (int s = 0; s < 8; s++) {
            int kb = s >> 1, b = s & 1;
            int w  = kb*8 + 4*b + q;
            float x0 = __ldg(cb + (size_t)c*OUT_DIM + 2*w);
            float x1 = __ldg(cb + (size_t)c*OUT_DIM + 2*w + 1);
            split_h2(x0, x1, hw[s], lw);
            sq += x0*x0 + x1*x1;
        }
        uint32_t* hrow = (uint32_t*)g_cbpack4 + c*CBW + q*8;
        *(uint4*)(hrow)     = make_uint4(hw[0], hw[1], hw[2], hw[3]);
        *(uint4*)(hrow + 4) = make_uint4(hw[4], hw[5], hw[6], hw[7]);
        sq += __shfl_xor_sync(0xffffffffu, sq, 1);
        sq += __shfl_xor_sync(0xffffffffu, sq, 2);
        if (q == 0) {
            g_e2[c] = sq;
            atomicMax(&g_e2max_bits, __float_as_int(sq));
        }
    } else if (gt < CODEBOOK*4 + 4096) {
        int widx = gt - CODEBOOK*4;
        const float* W; int off; int local;
        if (widx < 2048)      { W = W1; off = 0;    local = widx; }
        else if (widx < 3072) { W = W2; off = 2048; local = widx - 2048; }
        else                  { W = W3; off = 3072; local = widx - 3072; }
        int lane = local & 31;
        int nb   = (local >> 5) & 7;
        int kb   = local >> 8;
        int qq = lane & 3, rr = lane >> 2;
        int n  = nb*8 + rr;
        int k0 = kb*16 + 2*qq;
        float w00 = __ldg(W + (size_t)(k0    )*64 + n);
        float w01 = __ldg(W + (size_t)(k0 + 1)*64 + n);
        float w10 = __ldg(W + (size_t)(k0 + 8)*64 + n);
        float w11 = __ldg(W + (size_t)(k0 + 9)*64 + n);
        uint32_t b0h, b0l, b1h, b1l;
        split_h2(w00, w01, b0h, b0l);
        split_h2(w10, w11, b1h, b1l);
        g_wpack4[off + local] = make_uint4(b0h, b1h, b0l, b1l);
    }
}

// ---------------- staging: hi-only uint4 copy ----------------
__device__ __forceinline__ void b_ldg(int ch, int tid, uint4* v) {
    const uint4* hb = g_cbpack4 + (size_t)ch*CCH*(CBW/4);
    v[0] = __ldg(hb + tid);
    v[1] = __ldg(hb + tid + 256);
}
__device__ __forceinline__ void b_sts(uint32_t* bbuf, int tid, const uint4* v) {
#pragma unroll
    for (int i = 0; i < 2; i++) {
        int idx = tid + i*256;
        int c0 = idx >> 3, sub = idx & 7;
        *(uint4*)(bbuf + c0*B_ROW_W + sub*4) = v[i];
    }
}

// ---------------- exact fp32 rescore: d = e2 - 2 x.e (r7-verified) ----------------
__device__ __forceinline__ float rescore(const float* __restrict__ cb, const float* xsT,
                                          const float* e2s, int t, int c) {
    const float4* er = (const float4*)(cb + (size_t)c * OUT_DIM);
    float s = 0.0f;
#pragma unroll
    for (int j4 = 0; j4 < 16; j4++) {
        float4 e4 = __ldg(er + j4);
        int j = j4*4;
        s = fmaf(e4.x, xsT[(j  )*XT_STRIDE + t], s);
        s = fmaf(e4.y, xsT[(j+1)*XT_STRIDE + t], s);
        s = fmaf(e4.z, xsT[(j+2)*XT_STRIDE + t], s);
        s = fmaf(e4.w, xsT[(j+3)*XT_STRIDE + t], s);
    }
    return fmaf(-2.0f, s, e2s[c]);
}

// ---------------- fused kernel ----------------
__global__ void __launch_bounds__(NTHREADS, 2)
vq_main(const float* __restrict__ obs,
        const float* __restrict__ W1, const float* __restrict__ b1,
        const float* __restrict__ W2, const float* __restrict__ b2,
        const float* __restrict__ W3, const float* __restrict__ b3,
        const float* __restrict__ cb,
        float* __restrict__ out)
{
    extern __shared__ float sm[];
    __shared__ int wq_cnt[8];
    __shared__ int isLast;
    const int tid  = threadIdx.x;
    const int wid  = tid >> 5;
    const int lane = tid & 31;
    const int r    = lane >> 2;
    const int q    = lane & 3;
    const int tok0 = blockIdx.x * TB;
    const int tokw = wid * 16;

    for (int i = tid; i < CODEBOOK; i += NTHREADS) sm[OFF_E2 + i] = g_e2[i];

    // ================= MLP on tensor cores (r15 verbatim) =================
    {
        float acc[8][4];
#pragma unroll
        for (int nb = 0; nb < 8; nb++)
#pragma unroll
            for (int j = 0; j < 4; j++) acc[nb][j] = 0.f;

        const float* r0 = obs + (size_t)(tok0 + tokw + r)*IN_DIM;
        const float* r8 = r0 + 8*IN_DIM;

#pragma unroll
        for (int kb = 0; kb < 8; kb++) {
            int k0 = kb*16 + 2*q;
            float2 p0 = *(const float2*)(r0 + k0);
            float2 p1 = *(const float2*)(r8 + k0);
            float2 p2 = *(const float2*)(r0 + k0 + 8);
            float2 p3 = *(const float2*)(r8 + k0 + 8);
            uint32_t ah[4], al[4];
            split_h2(p0.x, p0.y, ah[0], al[0]);
            split_h2(p1.x, p1.y, ah[1], al[1]);
            split_h2(p2.x, p2.y, ah[2], al[2]);
            split_h2(p3.x, p3.y, ah[3], al[3]);
#pragma unroll
            for (int nb = 0; nb < 8; nb++) {
                uint4 wv = __ldg(g_wpack4 + (kb*8 + nb)*32 + lane);
                mma16(acc[nb], ah, wv.x, wv.y);
                mma16(acc[nb], ah, wv.z, wv.w);
                mma16(acc[nb], al, wv.x, wv.y);
            }
        }

        uint32_t Fh[4][4], Fl[4][4];
#pragma unroll
        for (int kb2 = 0; kb2 < 4; kb2++)
#pragma unroll
            for (int hf = 0; hf < 2; hf++) {
                int nb = kb2*2 + hf;
                float bb0 = __ldg(b1 + nb*8 + 2*q);
                float bb1 = __ldg(b1 + nb*8 + 2*q + 1);
                float h0 = fmaxf(acc[nb][0] + bb0, 0.f);
                float h1 = fmaxf(acc[nb][1] + bb1, 0.f);
                float h2 = fmaxf(acc[nb][2] + bb0, 0.f);
                float h3 = fmaxf(acc[nb][3] + bb1, 0.f);
                split_h2(h0, h1, Fh[kb2][hf*2],     Fl[kb2][hf*2]);
                split_h2(h2, h3, Fh[kb2][hf*2 + 1], Fl[kb2][hf*2 + 1]);
            }

        float acc2[8][4];
#pragma unroll
        for (int nb = 0; nb < 8; nb++)
#pragma unroll
            for (int j = 0; j < 4; j++) acc2[nb][j] = 0.f;
#pragma unroll
        for (int kb = 0; kb < 4; kb++)
#pragma unroll
            for (int nb = 0; nb < 8; nb++) {
                uint4 wv = __ldg(g_wpack4 + 2048 + (kb*8 + nb)*32 + lane);
                mma16(acc2[nb], Fh[kb], wv.x, wv.y);
                mma16(acc2[nb], Fh[kb], wv.z, wv.w);
                mma16(acc2[nb], Fl[kb], wv.x, wv.y);
            }

#pragma unroll
        for (int kb2 = 0; kb2 < 4; kb2++)
#pragma unroll
            for (int hf = 0; hf < 2; hf++) {
                int nb = kb2*2 + hf;
                float bb0 = __ldg(b2 + nb*8 + 2*q);
                float bb1 = __ldg(b2 + nb*8 + 2*q + 1);
                float h0 = fmaxf(acc2[nb][0] + bb0, 0.f);
                float h1 = fmaxf(acc2[nb][1] + bb1, 0.f);
                float h2 = fmaxf(acc2[nb][2] + bb0, 0.f);
                float h3 = fmaxf(acc2[nb][3] + bb1, 0.f);
                split_h2(h0, h1, Fh[kb2][hf*2],     Fl[kb2][hf*2]);
                split_h2(h2, h3, Fh[kb2][hf*2 + 1], Fl[kb2][hf*2 + 1]);
            }

#pragma unroll
        for (int nb = 0; nb < 8; nb++)
#pragma unroll
            for (int j = 0; j < 4; j++) acc[nb][j] = 0.f;
#pragma unroll
        for (int kb = 0; kb < 4; kb++)
#pragma unroll
            for (int nb = 0; nb < 8; nb++) {
                uint4 wv = __ldg(g_wpack4 + 3072 + (kb*8 + nb)*32 + lane);
                mma16(acc[nb], Fh[kb], wv.x, wv.y);
                mma16(acc[nb], Fh[kb], wv.z, wv.w);
                mma16(acc[nb], Fl[kb], wv.x, wv.y);
            }

        float* base = sm + OFF_XT;
#pragma unroll
        for (int nb = 0; nb < 8; nb++) {
            int n0 = nb*8 + 2*q;
            float bb0 = __ldg(b3 + n0);
            float bb1 = __ldg(b3 + n0 + 1);
            base[(n0    )*XT_STRIDE + tokw + r]     = acc[nb][0] + bb0;
            base[(n0 + 1)*XT_STRIDE + tokw + r]     = acc[nb][1] + bb1;
            base[(n0    )*XT_STRIDE + tokw + r + 8] = acc[nb][2] + bb0;
            base[(n0 + 1)*XT_STRIDE + tokw + r + 8] = acc[nb][3] + bb1;
        }
    }
    __syncthreads();

    // ========== A fragments: 2 m16 tiles per warp (r14/15 verbatim) ==========
    const float* xsT = sm + OFF_XT;
    const int wtile  = wid & 3;
    const int whalf  = wid >> 2;
    const int tokw32 = wtile * 32;

    uint32_t Ah[2][4][4], Al[2][4][4];
#pragma unroll
    for (int tl = 0; tl < 2; tl++)
#pragma unroll
        for (int kb = 0; kb < 4; kb++) {
            int k0 = kb*16;
            const float* x0 = xsT + tokw32 + tl*16;
            float v00 = x0[(k0 + 2*q    )*XT_STRIDE + r];
            float v01 = x0[(k0 + 2*q + 1)*XT_STRIDE + r];
            float v10 = x0[(k0 + 2*q    )*XT_STRIDE + r + 8];
            float v11 = x0[(k0 + 2*q + 1)*XT_STRIDE + r + 8];
            float v20 = x0[(k0 + 2*q + 8)*XT_STRIDE + r];
            float v21 = x0[(k0 + 2*q + 9)*XT_STRIDE + r];
            float v30 = x0[(k0 + 2*q + 8)*XT_STRIDE + r + 8];
            float v31 = x0[(k0 + 2*q + 9)*XT_STRIDE + r + 8];
            split_h2(v00, v01, Ah[tl][kb][0], Al[tl][kb][0]);
            split_h2(v10, v11, Ah[tl][kb][1], Al[tl][kb][1]);
            split_h2(v20, v21, Ah[tl][kb][2], Al[tl][kb][2]);
            split_h2(v30, v31, Ah[tl][kb][3], Al[tl][kb][3]);
        }

    // init tbl + counters while XT settles
    unsigned long long* tbl = (unsigned long long*)(sm + OFF_TBL);
    if (tid < TB) tbl[tid] = 0xFFFFFFFFFFFFFFFFull;
    if (tid < 8)  wq_cnt[tid] = 0;

    uint32_t* bw = (uint32_t*)(sm + OFF_B);
    const float* e2s = sm + OFF_E2;

    // ================= PASS 1: hh-only sweep, per-pair min (no indices) =================
    float bmin[4];
#pragma unroll
    for (int p = 0; p < 4; p++) bmin[p] = FLT_MAX;

    {
        uint4 st[2];
        b_ldg(0, tid, st);
        b_sts(bw, tid, st);
        __syncthreads();
    }
    for (int ch = 0; ch < NCH; ch++) {
        const int buf = ch % 3;
        uint4 pv[2];
        const bool more = (ch + 1 < NCH);
        if (more) b_ldg(ch + 1, tid, pv);

        const uint32_t* bb = bw + buf*B_TILE_W;
#pragma unroll
        for (int gp2 = 0; gp2 < 2; gp2++) {
            const uint32_t* pa = bb + (whalf*32 + gp2*16 + r)*B_ROW_W + q*8;
            const uint32_t* pb = pa + 8*B_ROW_W;
            uint4 h0a = *(const uint4*)(pa);
            uint4 h1a = *(const uint4*)(pa + 4);
            uint4 h0b = *(const uint4*)(pb);
            uint4 h1b = *(const uint4*)(pb + 4);

            float aa[2][4] = {{0,0,0,0},{0,0,0,0}};
            float ab[2][4] = {{0,0,0,0},{0,0,0,0}};
#pragma unroll
            for (int tl = 0; tl < 2; tl++) {
                mma16(aa[tl], Ah[tl][0], h0a.x, h0a.y);
                mma16(aa[tl], Ah[tl][1], h0a.z, h0a.w);
                mma16(aa[tl], Ah[tl][2], h1a.x, h1a.y);
                mma16(aa[tl], Ah[tl][3], h1a.z, h1a.w);
                mma16(ab[tl], Ah[tl][0], h0b.x, h0b.y);
                mma16(ab[tl], Ah[tl][1], h0b.z, h0b.w);
                mma16(ab[tl], Ah[tl][2], h1b.x, h1b.y);
                mma16(ab[tl], Ah[tl][3], h1b.z, h1b.w);
            }

            int codeA = ch*CCH + whalf*32 + gp2*16 + 2*q;
            int codeB = codeA + 8;
            float e2A0 = e2s[codeA], e2A1 = e2s[codeA + 1];
            float e2B0 = e2s[codeB], e2B1 = e2s[codeB + 1];
#pragma unroll
            for (int tl = 0; tl < 2; tl++) {
                int p0 = tl*2, p1 = tl*2 + 1;
                bmin[p0] = fminf(bmin[p0], fminf(fmaf(-2.f, aa[tl][0], e2A0),
                                                 fmaf(-2.f, aa[tl][1], e2A1)));
                bmin[p1] = fminf(bmin[p1], fminf(fmaf(-2.f, aa[tl][2], e2A0),
                                                 fmaf(-2.f, aa[tl][3], e2A1)));
                bmin[p0] = fminf(bmin[p0], fminf(fmaf(-2.f, ab[tl][0], e2B0),
                                                 fmaf(-2.f, ab[tl][1], e2B1)));
                bmin[p1] = fminf(bmin[p1], fminf(fmaf(-2.f, ab[tl][2], e2B0),
                                                 fmaf(-2.f, ab[tl][3], e2B1)));
            }
        }

        if (more) b_sts(bw + ((ch + 1) % 3)*B_TILE_W, tid, pv);
        __syncthreads();
    }

    // ---- inter-pass: per-token tau = min + 2*Md (fixed threshold) ----
#pragma unroll
    for (int m = 1; m <= 2; m <<= 1)
#pragma unroll
        for (int p = 0; p < 4; p++)
            bmin[p] = fminf(bmin[p], __shfl_xor_sync(0xffffffffu, bmin[p], m));
    float* sRedMin = sm + OFF_RED;
    if (q == 0) {
#pragma unroll
        for (int p = 0; p < 4; p++)
            sRedMin[(tokw32 + r + 8*p)*2 + whalf] = bmin[p];
    }
    __syncthreads();
    if (tid < TB) {
        float m1 = fminf(sRedMin[tid*2], sRedMin[tid*2 + 1]);
        float nx = 0.f;
#pragma unroll
        for (int j = 0; j < OUT_DIM; j++) {
            float xv = xsT[j*XT_STRIDE + tid];
            nx = fmaf(xv, xv, nx);
        }
        float emax = sqrtf(__int_as_float(g_e2max_bits));
        sm[OFF_TAU + tid] = m1 + TAU_C * sqrtf(nx) * emax + 1e-4f;
    }
    {   // stage pass-2 chunk 0 into buf 0 (overlaps tau computation)
        uint4 st[2];
        b_ldg(0, tid, st);
        b_sts(bw, tid, st);
    }
    __syncthreads();

    // ================= PASS 2: identical hh sweep, enqueue d <= tau =================
    float tauR[4];
#pragma unroll
    for (int p = 0; p < 4; p++) tauR[p] = sm[OFF_TAU + tokw32 + r + 8*p];
    uint32_t* wq = (uint32_t*)(sm + OFF_Q) + wid*QCAP;

    for (int ch = 0; ch < NCH; ch++) {
        const int buf = ch % 3;
        uint4 pv[2];
        const bool more = (ch + 1 < NCH);
        if (more) b_ldg(ch + 1, tid, pv);

        const uint32_t* bb = bw + buf*B_TILE_W;
#pragma unroll
        for (int gp2 = 0; gp2 < 2; gp2++) {
            const uint32_t* pa = bb + (whalf*32 + gp2*16 + r)*B_ROW_W + q*8;
            const uint32_t* pb = pa + 8*B_ROW_W;
            uint4 h0a = *(const uint4*)(pa);
            uint4 h1a = *(const uint4*)(pa + 4);
            uint4 h0b = *(const uint4*)(pb);
            uint4 h1b = *(const uint4*)(pb + 4);

            float aa[2][4] = {{0,0,0,0},{0,0,0,0}};
            float ab[2][4] = {{0,0,0,0},{0,0,0,0}};
#pragma unroll
            for (int tl = 0; tl < 2; tl++) {
                mma16(aa[tl], Ah[tl][0], h0a.x, h0a.y);
                mma16(aa[tl], Ah[tl][1], h0a.z, h0a.w);
                mma16(aa[tl], Ah[tl][2], h1a.x, h1a.y);
                mma16(aa[tl], Ah[tl][3], h1a.z, h1a.w);
                mma16(ab[tl], Ah[tl][0], h0b.x, h0b.y);
                mma16(ab[tl], Ah[tl][1], h0b.z, h0b.w);
                mma16(ab[tl], Ah[tl][2], h1b.x, h1b.y);
                mma16(ab[tl], Ah[tl][3], h1b.z, h1b.w);
            }

            int codeA = ch*CCH + whalf*32 + gp2*16 + 2*q;
            int codeB = codeA + 8;
            float e2A0 = e2s[codeA], e2A1 = e2s[codeA + 1];
            float e2B0 = e2s[codeB], e2B1 = e2s[codeB + 1];

            float d[2][8];
            bool hit = false;
#pragma unroll
            for (int tl = 0; tl < 2; tl++) {
                d[tl][0] = fmaf(-2.f, aa[tl][0], e2A0);
                d[tl][1] = fmaf(-2.f, aa[tl][1], e2A1);
                d[tl][2] = fmaf(-2.f, aa[tl][2], e2A0);
                d[tl][3] = fmaf(-2.f, aa[tl][3], e2A1);
                d[tl][4] = fmaf(-2.f, ab[tl][0], e2B0);
                d[tl][5] = fmaf(-2.f, ab[tl][1], e2B1);
                d[tl][6] = fmaf(-2.f, ab[tl][2], e2B0);
                d[tl][7] = fmaf(-2.f, ab[tl][3], e2B1);
                float t0 = tauR[tl*2], t1 = tauR[tl*2 + 1];
                hit |= (d[tl][0] <= t0) | (d[tl][1] <= t0) | (d[tl][2] <= t1) | (d[tl][3] <= t1);
                hit |= (d[tl][4] <= t0) | (d[tl][5] <= t0) | (d[tl][6] <= t1) | (d[tl][7] <= t1);
            }
            if (__ballot_sync(0xffffffffu, hit)) {
#pragma unroll
                for (int tl = 0; tl < 2; tl++) {
                    int t0 = tokw32 + r + 8*(tl*2);
                    int t1 = t0 + 8;
                    float ta = tauR[tl*2], tb = tauR[tl*2 + 1];
#pragma unroll
                    for (int jj = 0; jj < 8; jj++) {
                        float dv = d[tl][jj];
                        float tv = ((jj >> 1) & 1) ? tb : ta;
                        if (dv <= tv) {
                            int tt = ((jj >> 1) & 1) ? t1 : t0;
                            int cc = ((jj < 4) ? codeA : codeB) + (jj & 1);
                            int pos = atomicAdd(&wq_cnt[wid], 1);
                            if (pos < QCAP)
                                wq[pos] = ((uint32_t)tt << 11) | (uint32_t)cc;
                        }
                    }
                }
            }
        }

        if (more) b_sts(bw + ((ch + 1) % 3)*B_TILE_W, tid, pv);
        __syncthreads();
    }

    // ================= exact rescore of candidates =================
    int nq = wq_cnt[wid];
    int n  = nq < QCAP ? nq : QCAP;
    for (int i = lane; i < n; i += 32) {
        uint32_t e = wq[i];
        int t = e >> 11, c = e & 0x7FF;
        float dd = rescore(cb, xsT, e2s, t, c);
        unsigned long long key = ((unsigned long long)fkey(dd) << 32) | (unsigned)c;
        atomicMin(&tbl[t], key);
    }
    if (nq > QCAP) {   // overflow: exhaustive exact fallback (correctness guarantee)
        for (int s = 0; s < 32; s++) {
            int t = tokw32 + s;
            for (int c = lane; c < CODEBOOK; c += 32) {
                float dd = rescore(cb, xsT, e2s, t, c);
                unsigned long long key = ((unsigned long long)fkey(dd) << 32) | (unsigned)c;
                atomicMin(&tbl[t], key);
            }
        }
    }
    __syncthreads();

    // ---- idx write ----
    int* sIdx = (int*)(sm + OFF_RED);   // RED region dead now
    if (tid < TB) {
        int bc = (int)(tbl[tid] & 0xFFFFFFFFull);
        sIdx[tid] = bc;
        out[IDX_OFF + (size_t)(tok0 + tid)] = (float)bc;
    }
    __syncthreads();

    // ---- msg write + commitment-loss partial ----
    float part = 0.0f;
    for (int f = tid; f < TB*OUT_DIM; f += NTHREADS) {
        int t = f >> 6, j = f & 63;
        int c = sIdx[t];
        float qv = __ldg(cb + (size_t)c * OUT_DIM + j);
        float xv = xsT[j*XT_STRIDE + t];
        out[(size_t)(tok0 + t)*OUT_DIM + j] = xv + (qv - xv);
        float dd = qv - xv;
        part += dd * dd;
    }
#pragma unroll
    for (int o = 16; o > 0; o >>= 1)
        part += __shfl_down_sync(0xffffffffu, part, o);
    __shared__ float swred[8];
    if ((tid & 31) == 0) swred[tid >> 5] = part;
    __syncthreads();
    if (tid == 0) {
        float s = 0.0f;
#pragma unroll
        for (int w = 0; w < 8; w++) s += swred[w];
        g_partial[blockIdx.x] = s;
        __threadfence();
        isLast = (atomicAdd(&g_done, 1) == NBLOCKS - 1);
    }
    __syncthreads();

    if (isLast) {
        volatile float* gp = g_partial;
        float* red = sm + 512;
        red[tid] = gp[tid] + gp[tid + NTHREADS];
        __syncthreads();
        for (int o = NTHREADS/2; o > 0; o >>= 1) {
            if (tid < o) red[tid] += red[tid + o];
            __syncthreads();
        }
        if (tid == 0) {
            out[LOSS_OFF] = red[0] * (1.0f / (float)MSG_ELEMS);
            g_done = 0;
        }
    }
}

extern "C" void kernel_launch(void* const* d_in, const int* in_sizes, int n_in,
                              void* d_out, int out_size)
{
    const float* obs = (const float*)d_in[0];
    const float* W1  = (const float*)d_in[1];
    const float* b1  = (const float*)d_in[2];
    const float* W2  = (const float*)d_in[3];
    const float* b2  = (const float*)d_in[4];
    const float* W3  = (const float*)d_in[5];
    const float* b3  = (const float*)d_in[6];
    const float* cb  = (const float*)d_in[7];
    float* out = (float*)d_out;

    cudaFuncSetAttribute(vq_main, cudaFuncAttributeMaxDynamicSharedMemorySize,
                         SMEM_FLOATS * (int)sizeof(float));

    prep_kernel<<<(CODEBOOK*4 + 4096 + 255)/256, 256>>>(cb, W1, W2, W3);
    vq_main<<<NBLOCKS, NTHREADS, SMEM_FLOATS * sizeof(float)>>>(
        obs, W1, b1, W2, b2, W3, b3, cb, out);
}